// round 1
// baseline (speedup 1.0000x reference)
#include <cuda_runtime.h>
#include <cuda_bf16.h>
#include <math.h>

// Problem constants
#define BATCH 256
#define SEQL  200
#define INF   512      // layer input feature (IN = 512 = 2H, same for both layers)
#define HID   256
#define G3    768      // 3*H
#define BL    (BATCH*SEQL)   // 51200

// ---------------- scratch (device globals; no runtime allocation) ------------
__device__ float g_xi_f[(size_t)BL * G3];   // input-gate pre-activations, fwd dir
__device__ float g_xi_r[(size_t)BL * G3];   // input-gate pre-activations, bwd dir
__device__ float g_seq0[(size_t)BL * 512];  // layer-0 output [B, L, 2H]
__device__ float g_seq1[(size_t)BL * 512];  // layer-1 output [B, L, 2H]
__device__ float g_p[BL];                   // softmax(y)/10

// ---------------- f32x2 packed helpers (Blackwell sm_103a) -------------------
__device__ __forceinline__ unsigned long long dup2(float x) {
    unsigned long long r;
    asm("mov.b64 %0, {%1, %1};" : "=l"(r) : "r"(__float_as_uint(x)));
    return r;
}
__device__ __forceinline__ void ffma2(unsigned long long& d, unsigned long long a,
                                      unsigned long long b) {
    asm("fma.rn.f32x2 %0, %1, %2, %0;" : "+l"(d) : "l"(a), "l"(b));
}
__device__ __forceinline__ float f2lo(unsigned long long v) {
    return __uint_as_float((unsigned)v);
}
__device__ __forceinline__ float f2hi(unsigned long long v) {
    return __uint_as_float((unsigned)(v >> 32));
}

// ---------------- GEMM: C[M,768] = A[M,512] @ W[768,512]^T + bias ------------
// BM=128, BN=128, BK=8, 256 threads, per-thread 8x8 (4 m-pairs packed f32x2).
__global__ __launch_bounds__(256) void gemm_xi(
    int srcsel,            // 0: A = x (kernel arg), 1: A = g_seq0
    const float* __restrict__ x,
    const float* __restrict__ W,
    const float* __restrict__ bias,
    int dstsel)            // 0: C = g_xi_f, 1: C = g_xi_r
{
    const float* A = srcsel ? g_seq0 : x;
    float* C = dstsel ? g_xi_r : g_xi_f;

    __shared__ float As[8][132];
    __shared__ float Bs[8][132];

    const int m0 = blockIdx.y * 128;
    const int n0 = blockIdx.x * 128;
    const int tid = threadIdx.x;
    const int tx = tid & 15;       // n-tile: cols tx*8 .. +8
    const int ty = tid >> 4;       // m-tile: rows ty*8 .. +8 (4 f32x2 pairs)
    const int lr = tid >> 1;       // loader row 0..127
    const int lc = (tid & 1) * 4;  // loader k-offset 0 or 4

    unsigned long long acc[4][8];
#pragma unroll
    for (int p = 0; p < 4; p++)
#pragma unroll
        for (int j = 0; j < 8; j++) acc[p][j] = 0ull;

    const float* Aptr = A + (size_t)(m0 + lr) * INF + lc;
    const float* Wptr = W + (size_t)(n0 + lr) * INF + lc;

    for (int kt = 0; kt < INF; kt += 8) {
        float4 av = *(const float4*)(Aptr + kt);
        float4 wv = *(const float4*)(Wptr + kt);
        As[lc + 0][lr] = av.x; As[lc + 1][lr] = av.y;
        As[lc + 2][lr] = av.z; As[lc + 3][lr] = av.w;
        Bs[lc + 0][lr] = wv.x; Bs[lc + 1][lr] = wv.y;
        Bs[lc + 2][lr] = wv.z; Bs[lc + 3][lr] = wv.w;
        __syncthreads();
#pragma unroll
        for (int k = 0; k < 8; k++) {
            unsigned long long a2[4];
#pragma unroll
            for (int p = 0; p < 4; p++)
                a2[p] = *(const unsigned long long*)&As[k][ty * 8 + 2 * p];
            float4 b0 = *(const float4*)&Bs[k][tx * 8];
            float4 b1 = *(const float4*)&Bs[k][tx * 8 + 4];
            unsigned long long bd[8];
            bd[0] = dup2(b0.x); bd[1] = dup2(b0.y); bd[2] = dup2(b0.z); bd[3] = dup2(b0.w);
            bd[4] = dup2(b1.x); bd[5] = dup2(b1.y); bd[6] = dup2(b1.z); bd[7] = dup2(b1.w);
#pragma unroll
            for (int p = 0; p < 4; p++)
#pragma unroll
                for (int j = 0; j < 8; j++) ffma2(acc[p][j], a2[p], bd[j]);
        }
        __syncthreads();
    }

    // epilogue: add bias, store
    float bb[8];
#pragma unroll
    for (int j = 0; j < 8; j++) bb[j] = bias[n0 + tx * 8 + j];

#pragma unroll
    for (int p = 0; p < 4; p++) {
        const int m = m0 + ty * 8 + 2 * p;
        float4 r0, r1, s0, s1;
        r0.x = f2lo(acc[p][0]) + bb[0]; r0.y = f2lo(acc[p][1]) + bb[1];
        r0.z = f2lo(acc[p][2]) + bb[2]; r0.w = f2lo(acc[p][3]) + bb[3];
        r1.x = f2lo(acc[p][4]) + bb[4]; r1.y = f2lo(acc[p][5]) + bb[5];
        r1.z = f2lo(acc[p][6]) + bb[6]; r1.w = f2lo(acc[p][7]) + bb[7];
        s0.x = f2hi(acc[p][0]) + bb[0]; s0.y = f2hi(acc[p][1]) + bb[1];
        s0.z = f2hi(acc[p][2]) + bb[2]; s0.w = f2hi(acc[p][3]) + bb[3];
        s1.x = f2hi(acc[p][4]) + bb[4]; s1.y = f2hi(acc[p][5]) + bb[5];
        s1.z = f2hi(acc[p][6]) + bb[6]; s1.w = f2hi(acc[p][7]) + bb[7];
        float* cp0 = C + (size_t)m * G3 + n0 + tx * 8;
        float* cp1 = C + (size_t)(m + 1) * G3 + n0 + tx * 8;
        *(float4*)cp0 = r0; *(float4*)(cp0 + 4) = r1;
        *(float4*)cp1 = s0; *(float4*)(cp1 + 4) = s1;
    }
}

// ---------------- GRU step: one time step, both directions -------------------
// grid (8 h-tiles, 8 b-tiles, 2 dirs), 128 threads. Tile: 32 h x 32 b x 3 gates.
__global__ __launch_bounds__(128) void gru_step(
    const float* __restrict__ whh_f, const float* __restrict__ whh_r,
    const float* __restrict__ bhh_f, const float* __restrict__ bhh_r,
    int layer, int step)
{
    float* seq = layer ? g_seq1 : g_seq0;
    const int dir = blockIdx.z;
    const int t      = dir ? (SEQL - 1 - step) : step;
    const int t_prev = dir ? (t + 1) : (t - 1);
    const bool has_prev = (step > 0);
    const float* xi  = dir ? g_xi_r : g_xi_f;
    const float* whh = dir ? whh_r : whh_f;
    const float* bhh = dir ? bhh_r : bhh_f;
    const int zoff = dir * HID;

    const int h0 = blockIdx.x * 32;
    const int b0 = blockIdx.y * 32;
    const int tid = threadIdx.x;
    const int tx = tid & 31;   // h within tile
    const int ty = tid >> 5;   // batch group (8 batches = 4 f32x2 pairs)

    __shared__ float Hs[16][34];
    __shared__ float Ws[3][16][33];

    unsigned long long acc[3][4];
#pragma unroll
    for (int g = 0; g < 3; g++)
#pragma unroll
        for (int p = 0; p < 4; p++) acc[g][p] = 0ull;

    if (has_prev) {
        const int lb  = tid >> 2;        // 0..31
        const int lk4 = (tid & 3) * 4;   // 0,4,8,12
        for (int kt = 0; kt < HID; kt += 16) {
            float4 hv = *(const float4*)&seq[((size_t)(b0 + lb) * SEQL + t_prev) * 512 +
                                             zoff + kt + lk4];
            Hs[lk4 + 0][lb] = hv.x; Hs[lk4 + 1][lb] = hv.y;
            Hs[lk4 + 2][lb] = hv.z; Hs[lk4 + 3][lb] = hv.w;
#pragma unroll
            for (int g = 0; g < 3; g++) {
                float4 wv = *(const float4*)&whh[(size_t)(g * HID + h0 + lb) * HID +
                                                 kt + lk4];
                Ws[g][lk4 + 0][lb] = wv.x; Ws[g][lk4 + 1][lb] = wv.y;
                Ws[g][lk4 + 2][lb] = wv.z; Ws[g][lk4 + 3][lb] = wv.w;
            }
            __syncthreads();
#pragma unroll
            for (int kk = 0; kk < 16; kk++) {
                unsigned long long hh[4];
#pragma unroll
                for (int p = 0; p < 4; p++)
                    hh[p] = *(const unsigned long long*)&Hs[kk][ty * 8 + 2 * p];
#pragma unroll
                for (int g = 0; g < 3; g++) {
                    unsigned long long wd = dup2(Ws[g][kk][tx]);
#pragma unroll
                    for (int p = 0; p < 4; p++) ffma2(acc[g][p], hh[p], wd);
                }
            }
            __syncthreads();
        }
    }

    // epilogue: gates + hidden update
    const int h = h0 + tx;
    const float br = bhh[h], bz = bhh[HID + h], bn = bhh[2 * HID + h];
#pragma unroll
    for (int p = 0; p < 4; p++) {
#pragma unroll
        for (int half = 0; half < 2; half++) {
            const int b = b0 + ty * 8 + 2 * p + half;
            const float gr = (half ? f2hi(acc[0][p]) : f2lo(acc[0][p])) + br;
            const float gz = (half ? f2hi(acc[1][p]) : f2lo(acc[1][p])) + bz;
            const float gn = (half ? f2hi(acc[2][p]) : f2lo(acc[2][p])) + bn;
            const size_t xbase = ((size_t)b * SEQL + t) * G3 + h;
            const float ir = xi[xbase];
            const float iz = xi[xbase + HID];
            const float in_ = xi[xbase + 2 * HID];
            const float r = 1.f / (1.f + __expf(-(ir + gr)));
            const float z = 1.f / (1.f + __expf(-(iz + gz)));
            const float n = tanhf(in_ + r * gn);
            const float hp = has_prev
                ? seq[((size_t)b * SEQL + t_prev) * 512 + zoff + h] : 0.f;
            seq[((size_t)b * SEQL + t) * 512 + zoff + h] = (1.f - z) * n + z * hp;
        }
    }
}

// ---------------- heads ------------------------------------------------------
__global__ __launch_bounds__(128) void fc_heads(
    const float* __restrict__ fc1w, const float* __restrict__ fc1b,
    const float* __restrict__ fc2w, const float* __restrict__ fc2b,
    float* __restrict__ y, float* __restrict__ y2)
{
    const int bt = blockIdx.x;  // b*200 + t
    __shared__ float row[512];
    const int tid = threadIdx.x;
    const float* src = g_seq1 + (size_t)bt * 512;
    for (int i = tid; i < 512; i += 128) row[i] = src[i];
    __syncthreads();
    const int warp = tid >> 5, lane = tid & 31;
    for (int j = warp; j < 11; j += 4) {
        const float* w = (j == 10) ? fc1w : fc2w + (size_t)j * 512;
        float s = 0.f;
#pragma unroll
        for (int i = 0; i < 16; i++) s += row[lane + 32 * i] * w[lane + 32 * i];
#pragma unroll
        for (int off = 16; off; off >>= 1) s += __shfl_xor_sync(0xffffffffu, s, off);
        if (lane == 0) {
            if (j == 10) y[bt] = s + fc1b[0];
            else         y2[(size_t)bt * 10 + j] = s + fc2b[j];
        }
    }
}

__global__ __launch_bounds__(256) void softmax_y_kernel(const float* __restrict__ y) {
    const int b = blockIdx.x;
    __shared__ float sh[256];
    const int tid = threadIdx.x;
    float v = (tid < SEQL) ? y[b * SEQL + tid] : -INFINITY;
    sh[tid] = v; __syncthreads();
    for (int s = 128; s; s >>= 1) {
        if (tid < s) sh[tid] = fmaxf(sh[tid], sh[tid + s]);
        __syncthreads();
    }
    const float mx = sh[0]; __syncthreads();
    const float e = (tid < SEQL) ? __expf(v - mx) : 0.f;
    sh[tid] = e; __syncthreads();
    for (int s = 128; s; s >>= 1) {
        if (tid < s) sh[tid] += sh[tid + s];
        __syncthreads();
    }
    const float inv = 1.f / sh[0];
    if (tid < SEQL) g_p[b * SEQL + tid] = e * inv * 0.1f;
}

__global__ __launch_bounds__(256) void softmax_y2_kernel(
    const float* __restrict__ y2, float* __restrict__ y3)
{
    const int b = blockIdx.x;
    const int tid = threadIdx.x;
    __shared__ float sh[256];
    const float* src = y2 + (size_t)b * 2000;
    float mx = -INFINITY;
    for (int i = tid; i < 2000; i += 256) mx = fmaxf(mx, src[i]);
    sh[tid] = mx; __syncthreads();
    for (int s = 128; s; s >>= 1) {
        if (tid < s) sh[tid] = fmaxf(sh[tid], sh[tid + s]);
        __syncthreads();
    }
    mx = sh[0]; __syncthreads();
    float sum = 0.f;
    for (int i = tid; i < 2000; i += 256) sum += __expf(src[i] - mx);
    sh[tid] = sum; __syncthreads();
    for (int s = 128; s; s >>= 1) {
        if (tid < s) sh[tid] += sh[tid + s];
        __syncthreads();
    }
    const float inv = 1.f / sh[0];
    for (int i = tid; i < 2000; i += 256)
        y3[(size_t)b * 2000 + i] = __expf(src[i] - mx) * inv + g_p[b * SEQL + i / 10];
}

// ---------------- driver ------------------------------------------------------
extern "C" void kernel_launch(void* const* d_in, const int* in_sizes, int n_in,
                              void* d_out, int out_size) {
    (void)in_sizes; (void)n_in; (void)out_size;
    const float* x        = (const float*)d_in[0];
    const float* w_ih_l0  = (const float*)d_in[1];
    const float* w_hh_l0  = (const float*)d_in[2];
    const float* b_ih_l0  = (const float*)d_in[3];
    const float* b_hh_l0  = (const float*)d_in[4];
    const float* w_ih_l0r = (const float*)d_in[5];
    const float* w_hh_l0r = (const float*)d_in[6];
    const float* b_ih_l0r = (const float*)d_in[7];
    const float* b_hh_l0r = (const float*)d_in[8];
    const float* w_ih_l1  = (const float*)d_in[9];
    const float* w_hh_l1  = (const float*)d_in[10];
    const float* b_ih_l1  = (const float*)d_in[11];
    const float* b_hh_l1  = (const float*)d_in[12];
    const float* w_ih_l1r = (const float*)d_in[13];
    const float* w_hh_l1r = (const float*)d_in[14];
    const float* b_ih_l1r = (const float*)d_in[15];
    const float* b_hh_l1r = (const float*)d_in[16];
    const float* fc1_w    = (const float*)d_in[17];
    const float* fc1_b    = (const float*)d_in[18];
    const float* fc2_w    = (const float*)d_in[19];
    const float* fc2_b    = (const float*)d_in[20];

    float* y  = (float*)d_out;            // [256, 200]
    float* y2 = y + BL;                   // [256, 2000]
    float* y3 = y2 + BL * 10;             // [256, 2000]

    const dim3 ggrid(G3 / 128, BL / 128); // (6, 400)
    const dim3 sgrid(8, 8, 2);

    // Layer 0 input projections (both directions)
    gemm_xi<<<ggrid, 256>>>(0, x, w_ih_l0,  b_ih_l0,  0);
    gemm_xi<<<ggrid, 256>>>(0, x, w_ih_l0r, b_ih_l0r, 1);

    // Layer 0 recurrence
    for (int s = 0; s < SEQL; s++)
        gru_step<<<sgrid, 128>>>(w_hh_l0, w_hh_l0r, b_hh_l0, b_hh_l0r, 0, s);

    // Layer 1 input projections (input = g_seq0)
    gemm_xi<<<ggrid, 256>>>(1, nullptr, w_ih_l1,  b_ih_l1,  0);
    gemm_xi<<<ggrid, 256>>>(1, nullptr, w_ih_l1r, b_ih_l1r, 1);

    // Layer 1 recurrence
    for (int s = 0; s < SEQL; s++)
        gru_step<<<sgrid, 128>>>(w_hh_l1, w_hh_l1r, b_hh_l1, b_hh_l1r, 1, s);

    // Heads
    fc_heads<<<BL, 128>>>(fc1_w, fc1_b, fc2_w, fc2_b, y, y2);
    softmax_y_kernel<<<BATCH, 256>>>(y);
    softmax_y2_kernel<<<BATCH, 256>>>(y2, y3);
}

// round 2
// speedup vs baseline: 1.3467x; 1.3467x over previous
#include <cuda_runtime.h>
#include <cuda_bf16.h>
#include <math.h>

// Problem constants
#define BATCH 256
#define SEQL  200
#define INF   512
#define HID   256
#define G3    768
#define BL    (BATCH*SEQL)   // 51200

// ---------------- scratch (device globals) -----------------------------------
__device__ float g_xi_f[(size_t)BL * G3];
__device__ float g_xi_r[(size_t)BL * G3];
__device__ float g_seq0[(size_t)BL * 512];
__device__ float g_seq1[(size_t)BL * 512];
__device__ float g_p[BL];
__device__ float g_h[2][2][BATCH][HID];     // [parity][dir][b][h]
__device__ unsigned g_cnt[16];              // [dir*8 + batch-group]

// ---------------- f32x2 packed helpers ---------------------------------------
__device__ __forceinline__ unsigned long long dup2(float x) {
    unsigned long long r;
    asm("mov.b64 %0, {%1, %1};" : "=l"(r) : "r"(__float_as_uint(x)));
    return r;
}
__device__ __forceinline__ void ffma2(unsigned long long& d, unsigned long long a,
                                      unsigned long long b) {
    asm("fma.rn.f32x2 %0, %1, %2, %0;" : "+l"(d) : "l"(a), "l"(b));
}
__device__ __forceinline__ float f2lo(unsigned long long v) {
    return __uint_as_float((unsigned)v);
}
__device__ __forceinline__ float f2hi(unsigned long long v) {
    return __uint_as_float((unsigned)(v >> 32));
}
__device__ __forceinline__ unsigned ld_acq(const unsigned* p) {
    unsigned v;
    asm volatile("ld.acquire.gpu.global.u32 %0, [%1];" : "=r"(v) : "l"(p) : "memory");
    return v;
}
__device__ __forceinline__ void red_rel_add(unsigned* p, unsigned v) {
    asm volatile("red.release.gpu.global.add.u32 [%0], %1;" :: "l"(p), "r"(v) : "memory");
}

// ---------------- GEMM: C[M,768] = A[M,512] @ W[768,512]^T + bias ------------
__global__ __launch_bounds__(256) void gemm_xi(
    int srcsel, const float* __restrict__ x,
    const float* __restrict__ W, const float* __restrict__ bias, int dstsel)
{
    const float* A = srcsel ? g_seq0 : x;
    float* C = dstsel ? g_xi_r : g_xi_f;

    __shared__ float As[8][132];
    __shared__ float Bs[8][132];

    const int m0 = blockIdx.y * 128;
    const int n0 = blockIdx.x * 128;
    const int tid = threadIdx.x;
    const int tx = tid & 15;
    const int ty = tid >> 4;
    const int lr = tid >> 1;
    const int lc = (tid & 1) * 4;

    unsigned long long acc[4][8];
#pragma unroll
    for (int p = 0; p < 4; p++)
#pragma unroll
        for (int j = 0; j < 8; j++) acc[p][j] = 0ull;

    const float* Aptr = A + (size_t)(m0 + lr) * INF + lc;
    const float* Wptr = W + (size_t)(n0 + lr) * INF + lc;

    for (int kt = 0; kt < INF; kt += 8) {
        float4 av = *(const float4*)(Aptr + kt);
        float4 wv = *(const float4*)(Wptr + kt);
        As[lc + 0][lr] = av.x; As[lc + 1][lr] = av.y;
        As[lc + 2][lr] = av.z; As[lc + 3][lr] = av.w;
        Bs[lc + 0][lr] = wv.x; Bs[lc + 1][lr] = wv.y;
        Bs[lc + 2][lr] = wv.z; Bs[lc + 3][lr] = wv.w;
        __syncthreads();
#pragma unroll
        for (int k = 0; k < 8; k++) {
            unsigned long long a2[4];
#pragma unroll
            for (int p = 0; p < 4; p++)
                a2[p] = *(const unsigned long long*)&As[k][ty * 8 + 2 * p];
            float4 b0 = *(const float4*)&Bs[k][tx * 8];
            float4 b1 = *(const float4*)&Bs[k][tx * 8 + 4];
            unsigned long long bd[8];
            bd[0] = dup2(b0.x); bd[1] = dup2(b0.y); bd[2] = dup2(b0.z); bd[3] = dup2(b0.w);
            bd[4] = dup2(b1.x); bd[5] = dup2(b1.y); bd[6] = dup2(b1.z); bd[7] = dup2(b1.w);
#pragma unroll
            for (int p = 0; p < 4; p++)
#pragma unroll
                for (int j = 0; j < 8; j++) ffma2(acc[p][j], a2[p], bd[j]);
        }
        __syncthreads();
    }

    float bb[8];
#pragma unroll
    for (int j = 0; j < 8; j++) bb[j] = bias[n0 + tx * 8 + j];

#pragma unroll
    for (int p = 0; p < 4; p++) {
        const int m = m0 + ty * 8 + 2 * p;
        float4 r0, r1, s0, s1;
        r0.x = f2lo(acc[p][0]) + bb[0]; r0.y = f2lo(acc[p][1]) + bb[1];
        r0.z = f2lo(acc[p][2]) + bb[2]; r0.w = f2lo(acc[p][3]) + bb[3];
        r1.x = f2lo(acc[p][4]) + bb[4]; r1.y = f2lo(acc[p][5]) + bb[5];
        r1.z = f2lo(acc[p][6]) + bb[6]; r1.w = f2lo(acc[p][7]) + bb[7];
        s0.x = f2hi(acc[p][0]) + bb[0]; s0.y = f2hi(acc[p][1]) + bb[1];
        s0.z = f2hi(acc[p][2]) + bb[2]; s0.w = f2hi(acc[p][3]) + bb[3];
        s1.x = f2hi(acc[p][4]) + bb[4]; s1.y = f2hi(acc[p][5]) + bb[5];
        s1.z = f2hi(acc[p][6]) + bb[6]; s1.w = f2hi(acc[p][7]) + bb[7];
        float* cp0 = C + (size_t)m * G3 + n0 + tx * 8;
        float* cp1 = C + (size_t)(m + 1) * G3 + n0 + tx * 8;
        *(float4*)cp0 = r0; *(float4*)(cp0 + 4) = r1;
        *(float4*)cp1 = s0; *(float4*)(cp1 + 4) = s1;
    }
}

// ---------------- persistent GRU recurrence ----------------------------------
// 128 CTAs (1/SM): dir = bid>>6, hg = (bid&63)>>3 (32 h-cols), bg = bid&7 (32 batches).
// Weights resident in SMEM; hidden state double-buffered in global; per-(dir,bg)
// monotonic counters provide producer->consumer sync each step.
#define WS_STRIDE 33
#define HS_STRIDE 34
#define SMEM_WS_FLOATS (3 * 256 * WS_STRIDE)
#define SMEM_HS_FLOATS (256 * HS_STRIDE)
#define GRU_SMEM_BYTES ((SMEM_WS_FLOATS + SMEM_HS_FLOATS) * 4)

__global__ void __launch_bounds__(128, 1) reset_cnt_kernel() {
    if (threadIdx.x < 16) g_cnt[threadIdx.x] = 0;
}

__global__ void __launch_bounds__(128, 1) gru_persist(
    const float* __restrict__ whh_f, const float* __restrict__ whh_r,
    const float* __restrict__ bhh_f, const float* __restrict__ bhh_r,
    int layer)
{
    extern __shared__ float sm[];
    float* ws = sm;                       // [3*256 (g,k)][33] -> h
    float* hs = sm + SMEM_WS_FLOATS;      // [256 (k)][34] -> local batch

    const int bid = blockIdx.x;
    const int dir = bid >> 6;
    const int hg  = (bid & 63) >> 3;
    const int bg  = bid & 7;
    const int h0  = hg * 32;
    const int b0  = bg * 32;

    float* seq = layer ? g_seq1 : g_seq0;
    const float* xi  = dir ? g_xi_r : g_xi_f;
    const float* whh = dir ? whh_r : whh_f;
    const float* bhh = dir ? bhh_r : bhh_f;
    unsigned* cnt = &g_cnt[dir * 8 + bg];
    const int zoff = dir * HID;

    const int tid = threadIdx.x;
    const int tx = tid & 31;   // h within tile
    const int ty = tid >> 5;   // batch octet (8 batches = 4 pairs)

    // ---- load weight slice into SMEM, transposed to [g][k][h] ----
    {
        const int lh = tid >> 2;            // 0..31
        const int lk = (tid & 3) * 4;       // 0,4,8,12
        for (int g = 0; g < 3; g++) {
            const float* wrow = whh + (size_t)(g * HID + h0 + lh) * HID;
            for (int kk = 0; kk < 16; kk++) {
                int k = kk * 16 + lk;
                float4 w = *(const float4*)(wrow + k);
                ws[(g * 256 + k + 0) * WS_STRIDE + lh] = w.x;
                ws[(g * 256 + k + 1) * WS_STRIDE + lh] = w.y;
                ws[(g * 256 + k + 2) * WS_STRIDE + lh] = w.z;
                ws[(g * 256 + k + 3) * WS_STRIDE + lh] = w.w;
            }
        }
    }
    __syncthreads();

    const int h = h0 + tx;
    const float br = bhh[h], bz = bhh[HID + h], bn = bhh[2 * HID + h];

    for (int s = 0; s < SEQL; s++) {
        const int t = dir ? (SEQL - 1 - s) : s;

        unsigned long long acc[3][4];
#pragma unroll
        for (int g = 0; g < 3; g++)
#pragma unroll
            for (int p = 0; p < 4; p++) acc[g][p] = 0ull;

        if (s > 0) {
            if (tid == 0) {
                const unsigned target = 8u * (unsigned)s;
                while (ld_acq(cnt) < target) {}
            }
            __syncthreads();

            // stage h_prev[b0..b0+31][0..255] into hs[k][b_local]
            const float* hb = &g_h[(s - 1) & 1][dir][b0][0];
#pragma unroll
            for (int i = 0; i < 16; i++) {
                int idx = i * 128 + tid;
                int b = idx >> 6;
                int k4 = (idx & 63) * 4;
                float4 v = *(const float4*)&hb[b * HID + k4];
                hs[(k4 + 0) * HS_STRIDE + b] = v.x;
                hs[(k4 + 1) * HS_STRIDE + b] = v.y;
                hs[(k4 + 2) * HS_STRIDE + b] = v.z;
                hs[(k4 + 3) * HS_STRIDE + b] = v.w;
            }
            __syncthreads();

#pragma unroll 4
            for (int k = 0; k < 256; k++) {
                unsigned long long h2[4];
#pragma unroll
                for (int p = 0; p < 4; p++)
                    h2[p] = *(const unsigned long long*)&hs[k * HS_STRIDE + ty * 8 + 2 * p];
#pragma unroll
                for (int g = 0; g < 3; g++) {
                    unsigned long long wd = dup2(ws[(g * 256 + k) * WS_STRIDE + tx]);
#pragma unroll
                    for (int p = 0; p < 4; p++) ffma2(acc[g][p], h2[p], wd);
                }
            }
        }

        // ---- epilogue: gates + hidden update ----
#pragma unroll
        for (int p = 0; p < 4; p++) {
#pragma unroll
            for (int half = 0; half < 2; half++) {
                const int bl = ty * 8 + 2 * p + half;
                const int b = b0 + bl;
                const float gr = (half ? f2hi(acc[0][p]) : f2lo(acc[0][p])) + br;
                const float gz = (half ? f2hi(acc[1][p]) : f2lo(acc[1][p])) + bz;
                const float gn = (half ? f2hi(acc[2][p]) : f2lo(acc[2][p])) + bn;
                const size_t xbase = ((size_t)b * SEQL + t) * G3 + h;
                const float ir  = xi[xbase];
                const float iz  = xi[xbase + HID];
                const float in_ = xi[xbase + 2 * HID];
                const float rg = 1.f / (1.f + __expf(-(ir + gr)));
                const float zg = 1.f / (1.f + __expf(-(iz + gz)));
                const float ng = tanhf(in_ + rg * gn);
                const float hp = (s > 0) ? hs[h * HS_STRIDE + bl] : 0.f;
                const float hn = (1.f - zg) * ng + zg * hp;
                g_h[s & 1][dir][b][h] = hn;
                seq[((size_t)b * SEQL + t) * 512 + zoff + h] = hn;
            }
        }
        __threadfence();
        __syncthreads();
        if (tid == 0) red_rel_add(cnt, 1u);
    }
}

// ---------------- heads ------------------------------------------------------
__global__ __launch_bounds__(128) void fc_heads(
    const float* __restrict__ fc1w, const float* __restrict__ fc1b,
    const float* __restrict__ fc2w, const float* __restrict__ fc2b,
    float* __restrict__ y, float* __restrict__ y2)
{
    const int bt = blockIdx.x;
    __shared__ float row[512];
    const int tid = threadIdx.x;
    const float* src = g_seq1 + (size_t)bt * 512;
    for (int i = tid; i < 512; i += 128) row[i] = src[i];
    __syncthreads();
    const int warp = tid >> 5, lane = tid & 31;
    for (int j = warp; j < 11; j += 4) {
        const float* w = (j == 10) ? fc1w : fc2w + (size_t)j * 512;
        float s = 0.f;
#pragma unroll
        for (int i = 0; i < 16; i++) s += row[lane + 32 * i] * w[lane + 32 * i];
#pragma unroll
        for (int off = 16; off; off >>= 1) s += __shfl_xor_sync(0xffffffffu, s, off);
        if (lane == 0) {
            if (j == 10) y[bt] = s + fc1b[0];
            else         y2[(size_t)bt * 10 + j] = s + fc2b[j];
        }
    }
}

__global__ __launch_bounds__(256) void softmax_y_kernel(const float* __restrict__ y) {
    const int b = blockIdx.x;
    __shared__ float sh[256];
    const int tid = threadIdx.x;
    float v = (tid < SEQL) ? y[b * SEQL + tid] : -INFINITY;
    sh[tid] = v; __syncthreads();
    for (int s = 128; s; s >>= 1) {
        if (tid < s) sh[tid] = fmaxf(sh[tid], sh[tid + s]);
        __syncthreads();
    }
    const float mx = sh[0]; __syncthreads();
    const float e = (tid < SEQL) ? __expf(v - mx) : 0.f;
    sh[tid] = e; __syncthreads();
    for (int s = 128; s; s >>= 1) {
        if (tid < s) sh[tid] += sh[tid + s];
        __syncthreads();
    }
    const float inv = 1.f / sh[0];
    if (tid < SEQL) g_p[b * SEQL + tid] = e * inv * 0.1f;
}

__global__ __launch_bounds__(256) void softmax_y2_kernel(
    const float* __restrict__ y2, float* __restrict__ y3)
{
    const int b = blockIdx.x;
    const int tid = threadIdx.x;
    __shared__ float sh[256];
    const float* src = y2 + (size_t)b * 2000;
    float mx = -INFINITY;
    for (int i = tid; i < 2000; i += 256) mx = fmaxf(mx, src[i]);
    sh[tid] = mx; __syncthreads();
    for (int s = 128; s; s >>= 1) {
        if (tid < s) sh[tid] = fmaxf(sh[tid], sh[tid + s]);
        __syncthreads();
    }
    mx = sh[0]; __syncthreads();
    float sum = 0.f;
    for (int i = tid; i < 2000; i += 256) sum += __expf(src[i] - mx);
    sh[tid] = sum; __syncthreads();
    for (int s = 128; s; s >>= 1) {
        if (tid < s) sh[tid] += sh[tid + s];
        __syncthreads();
    }
    const float inv = 1.f / sh[0];
    for (int i = tid; i < 2000; i += 256)
        y3[(size_t)b * 2000 + i] = __expf(src[i] - mx) * inv + g_p[b * SEQL + i / 10];
}

// ---------------- driver ------------------------------------------------------
extern "C" void kernel_launch(void* const* d_in, const int* in_sizes, int n_in,
                              void* d_out, int out_size) {
    (void)in_sizes; (void)n_in; (void)out_size;
    const float* x        = (const float*)d_in[0];
    const float* w_ih_l0  = (const float*)d_in[1];
    const float* w_hh_l0  = (const float*)d_in[2];
    const float* b_ih_l0  = (const float*)d_in[3];
    const float* b_hh_l0  = (const float*)d_in[4];
    const float* w_ih_l0r = (const float*)d_in[5];
    const float* w_hh_l0r = (const float*)d_in[6];
    const float* b_ih_l0r = (const float*)d_in[7];
    const float* b_hh_l0r = (const float*)d_in[8];
    const float* w_ih_l1  = (const float*)d_in[9];
    const float* w_hh_l1  = (const float*)d_in[10];
    const float* b_ih_l1  = (const float*)d_in[11];
    const float* b_hh_l1  = (const float*)d_in[12];
    const float* w_ih_l1r = (const float*)d_in[13];
    const float* w_hh_l1r = (const float*)d_in[14];
    const float* b_ih_l1r = (const float*)d_in[15];
    const float* b_hh_l1r = (const float*)d_in[16];
    const float* fc1_w    = (const float*)d_in[17];
    const float* fc1_b    = (const float*)d_in[18];
    const float* fc2_w    = (const float*)d_in[19];
    const float* fc2_b    = (const float*)d_in[20];

    float* y  = (float*)d_out;
    float* y2 = y + BL;
    float* y3 = y2 + BL * 10;

    cudaFuncSetAttribute(gru_persist, cudaFuncAttributeMaxDynamicSharedMemorySize,
                         GRU_SMEM_BYTES);

    const dim3 ggrid(G3 / 128, BL / 128);

    // Layer 0 input projections
    gemm_xi<<<ggrid, 256>>>(0, x, w_ih_l0,  b_ih_l0,  0);
    gemm_xi<<<ggrid, 256>>>(0, x, w_ih_l0r, b_ih_l0r, 1);

    // Layer 0 recurrence (persistent)
    reset_cnt_kernel<<<1, 128>>>();
    gru_persist<<<128, 128, GRU_SMEM_BYTES>>>(w_hh_l0, w_hh_l0r, b_hh_l0, b_hh_l0r, 0);

    // Layer 1 input projections
    gemm_xi<<<ggrid, 256>>>(1, nullptr, w_ih_l1,  b_ih_l1,  0);
    gemm_xi<<<ggrid, 256>>>(1, nullptr, w_ih_l1r, b_ih_l1r, 1);

    // Layer 1 recurrence (persistent)
    reset_cnt_kernel<<<1, 128>>>();
    gru_persist<<<128, 128, GRU_SMEM_BYTES>>>(w_hh_l1, w_hh_l1r, b_hh_l1, b_hh_l1r, 1);

    // Heads
    fc_heads<<<BL, 128>>>(fc1_w, fc1_b, fc2_w, fc2_b, y, y2);
    softmax_y_kernel<<<BATCH, 256>>>(y);
    softmax_y2_kernel<<<BATCH, 256>>>(y2, y3);
}

// round 3
// speedup vs baseline: 1.7734x; 1.3168x over previous
#include <cuda_runtime.h>
#include <cuda_bf16.h>
#include <math.h>

// Problem constants
#define BATCH 256
#define SEQL  200
#define INF   512
#define HID   256
#define G3    768
#define BL    (BATCH*SEQL)   // 51200

// ---------------- scratch (device globals) -----------------------------------
__device__ float g_xi_f[(size_t)BL * G3];
__device__ float g_xi_r[(size_t)BL * G3];
__device__ float g_seq0[(size_t)BL * 512];
__device__ float g_seq1[(size_t)BL * 512];
__device__ float g_p[BL];

// ---------------- f32x2 packed helpers ---------------------------------------
__device__ __forceinline__ unsigned long long dup2(float x) {
    unsigned long long r;
    asm("mov.b64 %0, {%1, %1};" : "=l"(r) : "r"(__float_as_uint(x)));
    return r;
}
__device__ __forceinline__ void ffma2(unsigned long long& d, unsigned long long a,
                                      unsigned long long b) {
    asm("fma.rn.f32x2 %0, %1, %2, %0;" : "+l"(d) : "l"(a), "l"(b));
}
__device__ __forceinline__ unsigned long long add2(unsigned long long a,
                                                   unsigned long long b) {
    unsigned long long d;
    asm("add.rn.f32x2 %0, %1, %2;" : "=l"(d) : "l"(a), "l"(b));
    return d;
}
__device__ __forceinline__ float f2lo(unsigned long long v) {
    return __uint_as_float((unsigned)v);
}
__device__ __forceinline__ float f2hi(unsigned long long v) {
    return __uint_as_float((unsigned)(v >> 32));
}
__device__ __forceinline__ unsigned smem_u32(const void* p) {
    unsigned r;
    asm("{ .reg .u64 t; cvta.to.shared.u64 t, %1; cvt.u32.u64 %0, t; }"
        : "=r"(r) : "l"(p));
    return r;
}
__device__ __forceinline__ unsigned mapa_sh(unsigned addr, unsigned rank) {
    unsigned r;
    asm("mapa.shared::cluster.u32 %0, %1, %2;" : "=r"(r) : "r"(addr), "r"(rank));
    return r;
}
__device__ __forceinline__ void st_cluster_v2(unsigned addr, float x, float y) {
    asm volatile("st.shared::cluster.v2.f32 [%0], {%1, %2};"
                 :: "r"(addr), "f"(x), "f"(y) : "memory");
}
__device__ __forceinline__ void cluster_sync() {
    asm volatile("barrier.cluster.arrive.aligned;" ::: "memory");
    asm volatile("barrier.cluster.wait.aligned;" ::: "memory");
}
__device__ __forceinline__ unsigned ctarank() {
    unsigned r;
    asm("mov.u32 %0, %%cluster_ctarank;" : "=r"(r));
    return r;
}

// ---------------- GEMM: C[M,768] = A[M,512] @ W[768,512]^T + bias ------------
__global__ __launch_bounds__(256) void gemm_xi(
    int srcsel, const float* __restrict__ x,
    const float* __restrict__ W, const float* __restrict__ bias, int dstsel)
{
    const float* A = srcsel ? g_seq0 : x;
    float* C = dstsel ? g_xi_r : g_xi_f;

    __shared__ float As[8][132];
    __shared__ float Bs[8][132];

    const int m0 = blockIdx.y * 128;
    const int n0 = blockIdx.x * 128;
    const int tid = threadIdx.x;
    const int tx = tid & 15;
    const int ty = tid >> 4;
    const int lr = tid >> 1;
    const int lc = (tid & 1) * 4;

    unsigned long long acc[4][8];
#pragma unroll
    for (int p = 0; p < 4; p++)
#pragma unroll
        for (int j = 0; j < 8; j++) acc[p][j] = 0ull;

    const float* Aptr = A + (size_t)(m0 + lr) * INF + lc;
    const float* Wptr = W + (size_t)(n0 + lr) * INF + lc;

    for (int kt = 0; kt < INF; kt += 8) {
        float4 av = *(const float4*)(Aptr + kt);
        float4 wv = *(const float4*)(Wptr + kt);
        As[lc + 0][lr] = av.x; As[lc + 1][lr] = av.y;
        As[lc + 2][lr] = av.z; As[lc + 3][lr] = av.w;
        Bs[lc + 0][lr] = wv.x; Bs[lc + 1][lr] = wv.y;
        Bs[lc + 2][lr] = wv.z; Bs[lc + 3][lr] = wv.w;
        __syncthreads();
#pragma unroll
        for (int k = 0; k < 8; k++) {
            unsigned long long a2[4];
#pragma unroll
            for (int p = 0; p < 4; p++)
                a2[p] = *(const unsigned long long*)&As[k][ty * 8 + 2 * p];
            float4 b0 = *(const float4*)&Bs[k][tx * 8];
            float4 b1 = *(const float4*)&Bs[k][tx * 8 + 4];
            unsigned long long bd[8];
            bd[0] = dup2(b0.x); bd[1] = dup2(b0.y); bd[2] = dup2(b0.z); bd[3] = dup2(b0.w);
            bd[4] = dup2(b1.x); bd[5] = dup2(b1.y); bd[6] = dup2(b1.z); bd[7] = dup2(b1.w);
#pragma unroll
            for (int p = 0; p < 4; p++)
#pragma unroll
                for (int j = 0; j < 8; j++) ffma2(acc[p][j], a2[p], bd[j]);
        }
        __syncthreads();
    }

    float bb[8];
#pragma unroll
    for (int j = 0; j < 8; j++) bb[j] = bias[n0 + tx * 8 + j];

#pragma unroll
    for (int p = 0; p < 4; p++) {
        const int m = m0 + ty * 8 + 2 * p;
        float4 r0, r1, s0, s1;
        r0.x = f2lo(acc[p][0]) + bb[0]; r0.y = f2lo(acc[p][1]) + bb[1];
        r0.z = f2lo(acc[p][2]) + bb[2]; r0.w = f2lo(acc[p][3]) + bb[3];
        r1.x = f2lo(acc[p][4]) + bb[4]; r1.y = f2lo(acc[p][5]) + bb[5];
        r1.z = f2lo(acc[p][6]) + bb[6]; r1.w = f2lo(acc[p][7]) + bb[7];
        s0.x = f2hi(acc[p][0]) + bb[0]; s0.y = f2hi(acc[p][1]) + bb[1];
        s0.z = f2hi(acc[p][2]) + bb[2]; s0.w = f2hi(acc[p][3]) + bb[3];
        s1.x = f2hi(acc[p][4]) + bb[4]; s1.y = f2hi(acc[p][5]) + bb[5];
        s1.z = f2hi(acc[p][6]) + bb[6]; s1.w = f2hi(acc[p][7]) + bb[7];
        float* cp0 = C + (size_t)m * G3 + n0 + tx * 8;
        float* cp1 = C + (size_t)(m + 1) * G3 + n0 + tx * 8;
        *(float4*)cp0 = r0; *(float4*)(cp0 + 4) = r1;
        *(float4*)cp1 = s0; *(float4*)(cp1 + 4) = s1;
    }
}

// ---------------- cluster-persistent GRU recurrence ---------------------------
// Grid: 128 CTAs = 32 clusters of 4. cluster = (dir, 16-batch group);
// CTA rank owns h-rows [rank*64, rank*64+64) for all 3 gates, with its 192KB
// weight slice resident in SMEM. h_prev staged in SMEM [256 k][18]; handoff
// between steps via st.shared::cluster + barrier.cluster (no global traffic).
#define HSS 18                                 // hs row stride (floats)
#define WS_FLOATS  (3 * 256 * 64)              // 196608 floats
#define HS_FLOATS  (256 * HSS)                 // 4608
#define RED_FLOATS (4 * 32 * 24)               // 3072
#define GRU_SMEM_BYTES ((WS_FLOATS + HS_FLOATS + RED_FLOATS) * 4)  // 227328 B

__global__ void __launch_bounds__(256, 1) __cluster_dims__(4, 1, 1)
gru_cluster(const float* __restrict__ whh_f, const float* __restrict__ whh_r,
            const float* __restrict__ bhh_f, const float* __restrict__ bhh_r,
            int layer)
{
    extern __shared__ float sm[];
    float* ws  = sm;                            // [3*256 (g,k)][64 hloc]
    float* hs  = sm + WS_FLOATS;                // [256 k][18] (16 b used)
    float* red = sm + WS_FLOATS + HS_FLOATS;    // [4 warp][32 lane][24]

    const unsigned rank = ctarank();
    const int cid = blockIdx.x >> 2;
    const int dir = cid >> 4;
    const int bg  = cid & 15;                  // batches bg*16 .. +16

    float* seq = layer ? g_seq1 : g_seq0;
    const float* xi  = dir ? g_xi_r : g_xi_f;
    const float* whh = dir ? whh_r : whh_f;
    const float* bhh = dir ? bhh_r : bhh_f;
    const int zoff = dir * HID;

    const int tid  = threadIdx.x;
    const int w    = tid >> 5;
    const int lane = tid & 31;
    const int hh    = w & 1;          // h half (32)
    const int boct  = (w >> 1) & 1;   // batch octet
    const int khalf = w >> 2;         // k half (128)
    const int k0 = khalf * 128;

    // ---- stage weight slice into SMEM: ws[(g*256+k)*64 + hloc] ----
    if (tid < 192) {
        const int g  = tid / 64;
        const int hl = tid % 64;
        const float* wrow = whh + (size_t)(g * HID + rank * 64 + hl) * HID;
        for (int k4 = 0; k4 < 256; k4 += 4) {
            float4 v = *(const float4*)(wrow + k4);
            ws[(g * 256 + k4 + 0) * 64 + hl] = v.x;
            ws[(g * 256 + k4 + 1) * 64 + hl] = v.y;
            ws[(g * 256 + k4 + 2) * 64 + hl] = v.z;
            ws[(g * 256 + k4 + 3) * 64 + hl] = v.w;
        }
    }
    // zero hs (h0 = 0)
    for (int i = tid; i < HS_FLOATS; i += 256) hs[i] = 0.f;
    __syncthreads();

    const int hglob = rank * 64 + hh * 32 + lane;
    const float br = bhh[hglob], bz = bhh[HID + hglob], bn = bhh[2 * HID + hglob];
    const unsigned hs_row_u32 =
        smem_u32(hs) + (unsigned)((hglob * HSS + boct * 8) * 4);

    for (int s = 0; s < SEQL; s++) {
        const int t = dir ? (SEQL - 1 - s) : s;

        // ---- xi prefetch (khalf0 warps, consumed in epilogue) ----
        float xig[3][8];
        if (khalf == 0) {
#pragma unroll
            for (int j = 0; j < 8; j++) {
                const int b = bg * 16 + boct * 8 + j;
                const float* xp = xi + ((size_t)b * SEQL + t) * G3 + hglob;
#pragma unroll
                for (int g = 0; g < 3; g++) xig[g][j] = __ldg(xp + g * HID);
            }
        }

        // ---- main k-loop: gh partial over this warp's k half ----
        unsigned long long acc[3][4];
#pragma unroll
        for (int g = 0; g < 3; g++)
#pragma unroll
            for (int p = 0; p < 4; p++) acc[g][p] = 0ull;

#pragma unroll 4
        for (int k = k0; k < k0 + 128; k++) {
            unsigned long long h2[4];
#pragma unroll
            for (int p = 0; p < 4; p++)
                h2[p] = *(const unsigned long long*)&hs[k * HSS + boct * 8 + 2 * p];
#pragma unroll
            for (int g = 0; g < 3; g++) {
                const unsigned long long wd =
                    dup2(ws[(g * 256 + k) * 64 + hh * 32 + lane]);
#pragma unroll
                for (int p = 0; p < 4; p++) ffma2(acc[g][p], h2[p], wd);
            }
        }

        // ---- cross-k-half reduction ----
        if (khalf == 1) {
#pragma unroll
            for (int g = 0; g < 3; g++)
#pragma unroll
                for (int p = 0; p < 4; p++)
                    *(unsigned long long*)&red[((w - 4) * 32 + lane) * 24 +
                                               (g * 4 + p) * 2] = acc[g][p];
        }
        __syncthreads();

        float hnew[8];
        if (khalf == 0) {
#pragma unroll
            for (int g = 0; g < 3; g++)
#pragma unroll
                for (int p = 0; p < 4; p++)
                    acc[g][p] = add2(acc[g][p],
                        *(const unsigned long long*)&red[(w * 32 + lane) * 24 +
                                                         (g * 4 + p) * 2]);
            // ---- epilogue: gates + hidden update ----
#pragma unroll
            for (int p = 0; p < 4; p++) {
#pragma unroll
                for (int half = 0; half < 2; half++) {
                    const int j = 2 * p + half;
                    const int bl = boct * 8 + j;
                    const float gr = (half ? f2hi(acc[0][p]) : f2lo(acc[0][p])) + br;
                    const float gz = (half ? f2hi(acc[1][p]) : f2lo(acc[1][p])) + bz;
                    const float gn = (half ? f2hi(acc[2][p]) : f2lo(acc[2][p])) + bn;
                    const float rg = 1.f / (1.f + __expf(-(xig[0][j] + gr)));
                    const float zg = 1.f / (1.f + __expf(-(xig[1][j] + gz)));
                    const float ng = tanhf(xig[2][j] + rg * gn);
                    const float hp = hs[hglob * HSS + bl];
                    const float hn = (1.f - zg) * ng + zg * hp;
                    hnew[j] = hn;
                    const int b = bg * 16 + bl;
                    seq[((size_t)b * SEQL + t) * 512 + zoff + hglob] = hn;
                }
            }
        }

        cluster_sync();   // all CTAs done reading hs for step s

        if (khalf == 0) {
#pragma unroll
            for (unsigned r = 0; r < 4; r++) {
                const unsigned pa = mapa_sh(hs_row_u32, r);
                st_cluster_v2(pa +  0, hnew[0], hnew[1]);
                st_cluster_v2(pa +  8, hnew[2], hnew[3]);
                st_cluster_v2(pa + 16, hnew[4], hnew[5]);
                st_cluster_v2(pa + 24, hnew[6], hnew[7]);
            }
        }

        cluster_sync();   // h_{s} visible everywhere
    }
}

// ---------------- heads ------------------------------------------------------
__global__ __launch_bounds__(128) void fc_heads(
    const float* __restrict__ fc1w, const float* __restrict__ fc1b,
    const float* __restrict__ fc2w, const float* __restrict__ fc2b,
    float* __restrict__ y, float* __restrict__ y2)
{
    const int bt = blockIdx.x;
    __shared__ float row[512];
    const int tid = threadIdx.x;
    const float* src = g_seq1 + (size_t)bt * 512;
    for (int i = tid; i < 512; i += 128) row[i] = src[i];
    __syncthreads();
    const int warp = tid >> 5, lane = tid & 31;
    for (int j = warp; j < 11; j += 4) {
        const float* w = (j == 10) ? fc1w : fc2w + (size_t)j * 512;
        float s = 0.f;
#pragma unroll
        for (int i = 0; i < 16; i++) s += row[lane + 32 * i] * w[lane + 32 * i];
#pragma unroll
        for (int off = 16; off; off >>= 1) s += __shfl_xor_sync(0xffffffffu, s, off);
        if (lane == 0) {
            if (j == 10) y[bt] = s + fc1b[0];
            else         y2[(size_t)bt * 10 + j] = s + fc2b[j];
        }
    }
}

__global__ __launch_bounds__(256) void softmax_y_kernel(const float* __restrict__ y) {
    const int b = blockIdx.x;
    __shared__ float sh[256];
    const int tid = threadIdx.x;
    float v = (tid < SEQL) ? y[b * SEQL + tid] : -INFINITY;
    sh[tid] = v; __syncthreads();
    for (int s = 128; s; s >>= 1) {
        if (tid < s) sh[tid] = fmaxf(sh[tid], sh[tid + s]);
        __syncthreads();
    }
    const float mx = sh[0]; __syncthreads();
    const float e = (tid < SEQL) ? __expf(v - mx) : 0.f;
    sh[tid] = e; __syncthreads();
    for (int s = 128; s; s >>= 1) {
        if (tid < s) sh[tid] += sh[tid + s];
        __syncthreads();
    }
    const float inv = 1.f / sh[0];
    if (tid < SEQL) g_p[b * SEQL + tid] = e * inv * 0.1f;
}

__global__ __launch_bounds__(256) void softmax_y2_kernel(
    const float* __restrict__ y2, float* __restrict__ y3)
{
    const int b = blockIdx.x;
    const int tid = threadIdx.x;
    __shared__ float sh[256];
    const float* src = y2 + (size_t)b * 2000;
    float mx = -INFINITY;
    for (int i = tid; i < 2000; i += 256) mx = fmaxf(mx, src[i]);
    sh[tid] = mx; __syncthreads();
    for (int s = 128; s; s >>= 1) {
        if (tid < s) sh[tid] = fmaxf(sh[tid], sh[tid + s]);
        __syncthreads();
    }
    mx = sh[0]; __syncthreads();
    float sum = 0.f;
    for (int i = tid; i < 2000; i += 256) sum += __expf(src[i] - mx);
    sh[tid] = sum; __syncthreads();
    for (int s = 128; s; s >>= 1) {
        if (tid < s) sh[tid] += sh[tid + s];
        __syncthreads();
    }
    const float inv = 1.f / sh[0];
    for (int i = tid; i < 2000; i += 256)
        y3[(size_t)b * 2000 + i] = __expf(src[i] - mx) * inv + g_p[b * SEQL + i / 10];
}

// ---------------- driver ------------------------------------------------------
extern "C" void kernel_launch(void* const* d_in, const int* in_sizes, int n_in,
                              void* d_out, int out_size) {
    (void)in_sizes; (void)n_in; (void)out_size;
    const float* x        = (const float*)d_in[0];
    const float* w_ih_l0  = (const float*)d_in[1];
    const float* w_hh_l0  = (const float*)d_in[2];
    const float* b_ih_l0  = (const float*)d_in[3];
    const float* b_hh_l0  = (const float*)d_in[4];
    const float* w_ih_l0r = (const float*)d_in[5];
    const float* w_hh_l0r = (const float*)d_in[6];
    const float* b_ih_l0r = (const float*)d_in[7];
    const float* b_hh_l0r = (const float*)d_in[8];
    const float* w_ih_l1  = (const float*)d_in[9];
    const float* w_hh_l1  = (const float*)d_in[10];
    const float* b_ih_l1  = (const float*)d_in[11];
    const float* b_hh_l1  = (const float*)d_in[12];
    const float* w_ih_l1r = (const float*)d_in[13];
    const float* w_hh_l1r = (const float*)d_in[14];
    const float* b_ih_l1r = (const float*)d_in[15];
    const float* b_hh_l1r = (const float*)d_in[16];
    const float* fc1_w    = (const float*)d_in[17];
    const float* fc1_b    = (const float*)d_in[18];
    const float* fc2_w    = (const float*)d_in[19];
    const float* fc2_b    = (const float*)d_in[20];

    float* y  = (float*)d_out;
    float* y2 = y + BL;
    float* y3 = y2 + BL * 10;

    static int configured = 0;
    if (!configured) {
        cudaFuncSetAttribute(gru_cluster, cudaFuncAttributeMaxDynamicSharedMemorySize,
                             GRU_SMEM_BYTES);
        configured = 1;
    }

    const dim3 ggrid(G3 / 128, BL / 128);

    // Layer 0 input projections
    gemm_xi<<<ggrid, 256>>>(0, x, w_ih_l0,  b_ih_l0,  0);
    gemm_xi<<<ggrid, 256>>>(0, x, w_ih_l0r, b_ih_l0r, 1);

    // Layer 0 recurrence (cluster-persistent)
    gru_cluster<<<128, 256, GRU_SMEM_BYTES>>>(w_hh_l0, w_hh_l0r, b_hh_l0, b_hh_l0r, 0);

    // Layer 1 input projections
    gemm_xi<<<ggrid, 256>>>(1, nullptr, w_ih_l1,  b_ih_l1,  0);
    gemm_xi<<<ggrid, 256>>>(1, nullptr, w_ih_l1r, b_ih_l1r, 1);

    // Layer 1 recurrence (cluster-persistent)
    gru_cluster<<<128, 256, GRU_SMEM_BYTES>>>(w_hh_l1, w_hh_l1r, b_hh_l1, b_hh_l1r, 1);

    // Heads
    fc_heads<<<BL, 128>>>(fc1_w, fc1_b, fc2_w, fc2_b, y, y2);
    softmax_y_kernel<<<BATCH, 256>>>(y);
    softmax_y2_kernel<<<BATCH, 256>>>(y2, y3);
}

// round 4
// speedup vs baseline: 1.8675x; 1.0531x over previous
#include <cuda_runtime.h>
#include <cuda_bf16.h>
#include <math.h>

// Problem constants
#define BATCH 256
#define SEQL  200
#define INF   512
#define HID   256
#define G3    768
#define BL    (BATCH*SEQL)   // 51200

// ---------------- scratch (device globals) -----------------------------------
__device__ float g_xi_f[(size_t)BL * G3];
__device__ float g_xi_r[(size_t)BL * G3];
__device__ float g_seq0[(size_t)BL * 512];
__device__ float g_seq1[(size_t)BL * 512];
__device__ float g_p[BL];

// ---------------- f32x2 packed helpers ---------------------------------------
__device__ __forceinline__ unsigned long long dup2(float x) {
    unsigned long long r;
    asm("mov.b64 %0, {%1, %1};" : "=l"(r) : "r"(__float_as_uint(x)));
    return r;
}
__device__ __forceinline__ void ffma2(unsigned long long& d, unsigned long long a,
                                      unsigned long long b) {
    asm("fma.rn.f32x2 %0, %1, %2, %0;" : "+l"(d) : "l"(a), "l"(b));
}
__device__ __forceinline__ unsigned long long add2(unsigned long long a,
                                                   unsigned long long b) {
    unsigned long long d;
    asm("add.rn.f32x2 %0, %1, %2;" : "=l"(d) : "l"(a), "l"(b));
    return d;
}
__device__ __forceinline__ float f2lo(unsigned long long v) {
    return __uint_as_float((unsigned)v);
}
__device__ __forceinline__ float f2hi(unsigned long long v) {
    return __uint_as_float((unsigned)(v >> 32));
}
__device__ __forceinline__ unsigned smem_u32(const void* p) {
    unsigned r;
    asm("{ .reg .u64 t; cvta.to.shared.u64 t, %1; cvt.u32.u64 %0, t; }"
        : "=r"(r) : "l"(p));
    return r;
}
__device__ __forceinline__ unsigned mapa_sh(unsigned addr, unsigned rank) {
    unsigned r;
    asm("mapa.shared::cluster.u32 %0, %1, %2;" : "=r"(r) : "r"(addr), "r"(rank));
    return r;
}
__device__ __forceinline__ void st_cluster_v2(unsigned addr, float x, float y) {
    asm volatile("st.shared::cluster.v2.f32 [%0], {%1, %2};"
                 :: "r"(addr), "f"(x), "f"(y) : "memory");
}
__device__ __forceinline__ void cluster_arrive() {
    asm volatile("barrier.cluster.arrive.aligned;" ::: "memory");
}
__device__ __forceinline__ void cluster_wait() {
    asm volatile("barrier.cluster.wait.aligned;" ::: "memory");
}
__device__ __forceinline__ unsigned ctarank() {
    unsigned r;
    asm("mov.u32 %0, %%cluster_ctarank;" : "=r"(r));
    return r;
}
// fast, saturation-safe activations (~1e-7 rel err)
__device__ __forceinline__ float sigmoid_f(float x) {
    return __fdividef(1.f, 1.f + __expf(-x));
}
__device__ __forceinline__ float tanh_f(float x) {
    return 1.f - __fdividef(2.f, __expf(2.f * x) + 1.f);
}

// ---------------- GEMM: C[M,768] = A[M,512] @ W[768,512]^T + bias ------------
// BM=128, BN=128, BK=8, double-buffered SMEM, 1 syncthreads per tile,
// LDG for tile t+1 hidden under compute(t).
__global__ __launch_bounds__(256) void gemm_xi(
    int srcsel, const float* __restrict__ x,
    const float* __restrict__ W, const float* __restrict__ bias, int dstsel)
{
    const float* A = srcsel ? g_seq0 : x;
    float* C = dstsel ? g_xi_r : g_xi_f;

    __shared__ float As[2][8][132];
    __shared__ float Bs[2][8][132];

    const int m0 = blockIdx.y * 128;
    const int n0 = blockIdx.x * 128;
    const int tid = threadIdx.x;
    const int tx = tid & 15;
    const int ty = tid >> 4;
    const int lr = tid >> 1;
    const int lc = (tid & 1) * 4;

    unsigned long long acc[4][8];
#pragma unroll
    for (int p = 0; p < 4; p++)
#pragma unroll
        for (int j = 0; j < 8; j++) acc[p][j] = 0ull;

    const float* Aptr = A + (size_t)(m0 + lr) * INF + lc;
    const float* Wptr = W + (size_t)(n0 + lr) * INF + lc;

    float4 av = *(const float4*)(Aptr);
    float4 wv = *(const float4*)(Wptr);

    for (int t = 0; t < 64; t++) {
        const int buf = t & 1;
        As[buf][lc + 0][lr] = av.x; As[buf][lc + 1][lr] = av.y;
        As[buf][lc + 2][lr] = av.z; As[buf][lc + 3][lr] = av.w;
        Bs[buf][lc + 0][lr] = wv.x; Bs[buf][lc + 1][lr] = wv.y;
        Bs[buf][lc + 2][lr] = wv.z; Bs[buf][lc + 3][lr] = wv.w;
        __syncthreads();
        if (t < 63) {
            av = *(const float4*)(Aptr + (t + 1) * 8);
            wv = *(const float4*)(Wptr + (t + 1) * 8);
        }
#pragma unroll
        for (int k = 0; k < 8; k++) {
            unsigned long long a2[4];
#pragma unroll
            for (int p = 0; p < 4; p++)
                a2[p] = *(const unsigned long long*)&As[buf][k][ty * 8 + 2 * p];
            float4 b0 = *(const float4*)&Bs[buf][k][tx * 8];
            float4 b1 = *(const float4*)&Bs[buf][k][tx * 8 + 4];
            unsigned long long bd[8];
            bd[0] = dup2(b0.x); bd[1] = dup2(b0.y); bd[2] = dup2(b0.z); bd[3] = dup2(b0.w);
            bd[4] = dup2(b1.x); bd[5] = dup2(b1.y); bd[6] = dup2(b1.z); bd[7] = dup2(b1.w);
#pragma unroll
            for (int p = 0; p < 4; p++)
#pragma unroll
                for (int j = 0; j < 8; j++) ffma2(acc[p][j], a2[p], bd[j]);
        }
    }

    float bb[8];
#pragma unroll
    for (int j = 0; j < 8; j++) bb[j] = bias[n0 + tx * 8 + j];

#pragma unroll
    for (int p = 0; p < 4; p++) {
        const int m = m0 + ty * 8 + 2 * p;
        float4 r0, r1, s0, s1;
        r0.x = f2lo(acc[p][0]) + bb[0]; r0.y = f2lo(acc[p][1]) + bb[1];
        r0.z = f2lo(acc[p][2]) + bb[2]; r0.w = f2lo(acc[p][3]) + bb[3];
        r1.x = f2lo(acc[p][4]) + bb[4]; r1.y = f2lo(acc[p][5]) + bb[5];
        r1.z = f2lo(acc[p][6]) + bb[6]; r1.w = f2lo(acc[p][7]) + bb[7];
        s0.x = f2hi(acc[p][0]) + bb[0]; s0.y = f2hi(acc[p][1]) + bb[1];
        s0.z = f2hi(acc[p][2]) + bb[2]; s0.w = f2hi(acc[p][3]) + bb[3];
        s1.x = f2hi(acc[p][4]) + bb[4]; s1.y = f2hi(acc[p][5]) + bb[5];
        s1.z = f2hi(acc[p][6]) + bb[6]; s1.w = f2hi(acc[p][7]) + bb[7];
        float* cp0 = C + (size_t)m * G3 + n0 + tx * 8;
        float* cp1 = C + (size_t)(m + 1) * G3 + n0 + tx * 8;
        *(float4*)cp0 = r0; *(float4*)(cp0 + 4) = r1;
        *(float4*)cp1 = s0; *(float4*)(cp1 + 4) = s1;
    }
}

// ---------------- cluster-persistent GRU recurrence ---------------------------
// 32 clusters of 4 CTAs; cluster = (dir, 16-batch group); CTA rank owns 64 h rows
// x 3 gates (192KB weights in SMEM). Split cluster barriers overlap their latency
// with the epilogue / next-step xi prefetch. Epilogue balanced across all warps.
#define HSS 18
#define WS_FLOATS  (3 * 256 * 64)              // 196608 floats
#define HS_FLOATS  (256 * HSS)                 // 4608
#define RED_FLOATS (8 * 32 * 12)               // 3072
#define GRU_SMEM_BYTES ((WS_FLOATS + HS_FLOATS + RED_FLOATS) * 4)  // 227328 B

__global__ void __launch_bounds__(256, 1) __cluster_dims__(4, 1, 1)
gru_cluster(const float* __restrict__ whh_f, const float* __restrict__ whh_r,
            const float* __restrict__ bhh_f, const float* __restrict__ bhh_r,
            int layer)
{
    extern __shared__ float sm[];
    float* ws  = sm;                            // [3*256 (g,k)][64 hloc]
    float* hs  = sm + WS_FLOATS;                // [256 k][HSS] (16 b used)
    float* red = sm + WS_FLOATS + HS_FLOATS;    // [8 warp][32 lane][12]

    const unsigned rank = ctarank();
    const int cid = blockIdx.x >> 2;
    const int dir = cid >> 4;
    const int bg  = cid & 15;

    float* seq = layer ? g_seq1 : g_seq0;
    const float* xi  = dir ? g_xi_r : g_xi_f;
    const float* whh = dir ? whh_r : whh_f;
    const float* bhh = dir ? bhh_r : bhh_f;
    const int zoff = dir * HID;

    const int tid  = threadIdx.x;
    const int w    = tid >> 5;
    const int lane = tid & 31;
    const int hh    = w & 1;          // h half (32)
    const int boct  = (w >> 1) & 1;   // batch octet
    const int khalf = w >> 2;         // k half (128)
    const int k0 = khalf * 128;
    const int jb = khalf * 4;         // this warp's 4 epilogue batches within octet

    // ---- stage weight slice into SMEM ----
    if (tid < 192) {
        const int g  = tid / 64;
        const int hl = tid % 64;
        const float* wrow = whh + (size_t)(g * HID + rank * 64 + hl) * HID;
        for (int k4 = 0; k4 < 256; k4 += 4) {
            float4 v = *(const float4*)(wrow + k4);
            ws[(g * 256 + k4 + 0) * 64 + hl] = v.x;
            ws[(g * 256 + k4 + 1) * 64 + hl] = v.y;
            ws[(g * 256 + k4 + 2) * 64 + hl] = v.z;
            ws[(g * 256 + k4 + 3) * 64 + hl] = v.w;
        }
    }
    for (int i = tid; i < HS_FLOATS; i += 256) hs[i] = 0.f;   // h0 = 0
    __syncthreads();

    const int hglob = rank * 64 + hh * 32 + lane;
    const float br = bhh[hglob], bz = bhh[HID + hglob], bn = bhh[2 * HID + hglob];
    const unsigned hs_dst_u32 =
        smem_u32(hs) + (unsigned)((hglob * HSS + boct * 8 + jb) * 4);
    unsigned hs_dst_r[4];
#pragma unroll
    for (unsigned r = 0; r < 4; r++) hs_dst_r[r] = mapa_sh(hs_dst_u32, r);

    // initial xi prefetch (step 0)
    float xig[3][4];
#pragma unroll
    for (int j = 0; j < 4; j++) {
        const int b = bg * 16 + boct * 8 + jb + j;
        const int t0 = dir ? (SEQL - 1) : 0;
        const float* xp = xi + ((size_t)b * SEQL + t0) * G3 + hglob;
#pragma unroll
        for (int g = 0; g < 3; g++) xig[g][j] = __ldg(xp + g * HID);
    }

    for (int s = 0; s < SEQL; s++) {
        const int t = dir ? (SEQL - 1 - s) : s;

        // ---- k-loop: gh partial over this warp's k half ----
        unsigned long long acc[3][4];
#pragma unroll
        for (int g = 0; g < 3; g++)
#pragma unroll
            for (int p = 0; p < 4; p++) acc[g][p] = 0ull;

#pragma unroll 4
        for (int k = k0; k < k0 + 128; k++) {
            unsigned long long h2[4];
#pragma unroll
            for (int p = 0; p < 4; p++)
                h2[p] = *(const unsigned long long*)&hs[k * HSS + boct * 8 + 2 * p];
#pragma unroll
            for (int g = 0; g < 3; g++) {
                const unsigned long long wd =
                    dup2(ws[(g * 256 + k) * 64 + hh * 32 + lane]);
#pragma unroll
                for (int p = 0; p < 4; p++) ffma2(acc[g][p], h2[p], wd);
            }
        }

        // hp for this warp's 4 batches (last hs reads of this step)
        float hp[4];
#pragma unroll
        for (int j = 0; j < 4; j++) hp[j] = hs[hglob * HSS + boct * 8 + jb + j];

        cluster_arrive();   // done READING hs; latency hidden under epilogue

        // ---- exchange complementary partials between khalf pairs ----
        // khalf0 keeps p=0,1 / exports p=2,3 ; khalf1 keeps p=2,3 / exports p=0,1
        {
            float* myred = &red[(w * 32 + lane) * 12];
            const int pe = khalf ? 0 : 2;   // exported p base
#pragma unroll
            for (int g = 0; g < 3; g++) {
                *(unsigned long long*)&myred[(g * 2 + 0) * 2] = acc[g][pe + 0];
                *(unsigned long long*)&myred[(g * 2 + 1) * 2] = acc[g][pe + 1];
            }
        }
        __syncthreads();
        {
            const int peer = khalf ? (w - 4) : (w + 4);
            const float* pr = &red[(peer * 32 + lane) * 12];
            const int pk = khalf ? 2 : 0;   // kept p base
#pragma unroll
            for (int g = 0; g < 3; g++) {
                acc[g][pk + 0] = add2(acc[g][pk + 0],
                                      *(const unsigned long long*)&pr[(g * 2 + 0) * 2]);
                acc[g][pk + 1] = add2(acc[g][pk + 1],
                                      *(const unsigned long long*)&pr[(g * 2 + 1) * 2]);
            }
            // move kept accs to slots 0,1 for uniform epilogue
            if (pk) {
#pragma unroll
                for (int g = 0; g < 3; g++) { acc[g][0] = acc[g][2]; acc[g][1] = acc[g][3]; }
            }
        }

        // ---- epilogue: 4 batches per warp ----
        float hnew[4];
#pragma unroll
        for (int p = 0; p < 2; p++) {
#pragma unroll
            for (int half = 0; half < 2; half++) {
                const int j = 2 * p + half;
                const float gr = (half ? f2hi(acc[0][p]) : f2lo(acc[0][p])) + br;
                const float gz = (half ? f2hi(acc[1][p]) : f2lo(acc[1][p])) + bz;
                const float gn = (half ? f2hi(acc[2][p]) : f2lo(acc[2][p])) + bn;
                const float rg = sigmoid_f(xig[0][j] + gr);
                const float zg = sigmoid_f(xig[1][j] + gz);
                const float ng = tanh_f(xig[2][j] + rg * gn);
                hnew[j] = (1.f - zg) * ng + zg * hp[j];
                const int b = bg * 16 + boct * 8 + jb + j;
                seq[((size_t)b * SEQL + t) * 512 + zoff + hglob] = hnew[j];
            }
        }

        cluster_wait();     // everyone done reading hs -> safe to overwrite

        // ---- distribute h_new to all 4 ranks' hs via DSMEM ----
#pragma unroll
        for (unsigned r = 0; r < 4; r++) {
            st_cluster_v2(hs_dst_r[r] + 0, hnew[0], hnew[1]);
            st_cluster_v2(hs_dst_r[r] + 8, hnew[2], hnew[3]);
        }

        cluster_arrive();   // stores released; latency hidden under xi prefetch

        if (s + 1 < SEQL) {
            const int tn = dir ? (SEQL - 2 - s) : (s + 1);
#pragma unroll
            for (int j = 0; j < 4; j++) {
                const int b = bg * 16 + boct * 8 + jb + j;
                const float* xp = xi + ((size_t)b * SEQL + tn) * G3 + hglob;
#pragma unroll
                for (int g = 0; g < 3; g++) xig[g][j] = __ldg(xp + g * HID);
            }
        }

        cluster_wait();     // h_s visible everywhere
    }
}

// ---------------- heads ------------------------------------------------------
__global__ __launch_bounds__(128) void fc_heads(
    const float* __restrict__ fc1w, const float* __restrict__ fc1b,
    const float* __restrict__ fc2w, const float* __restrict__ fc2b,
    float* __restrict__ y, float* __restrict__ y2)
{
    const int bt = blockIdx.x;
    __shared__ float row[512];
    const int tid = threadIdx.x;
    const float* src = g_seq1 + (size_t)bt * 512;
    for (int i = tid; i < 512; i += 128) row[i] = src[i];
    __syncthreads();
    const int warp = tid >> 5, lane = tid & 31;
    for (int j = warp; j < 11; j += 4) {
        const float* w = (j == 10) ? fc1w : fc2w + (size_t)j * 512;
        float s = 0.f;
#pragma unroll
        for (int i = 0; i < 16; i++) s += row[lane + 32 * i] * w[lane + 32 * i];
#pragma unroll
        for (int off = 16; off; off >>= 1) s += __shfl_xor_sync(0xffffffffu, s, off);
        if (lane == 0) {
            if (j == 10) y[bt] = s + fc1b[0];
            else         y2[(size_t)bt * 10 + j] = s + fc2b[j];
        }
    }
}

__global__ __launch_bounds__(256) void softmax_y_kernel(const float* __restrict__ y) {
    const int b = blockIdx.x;
    __shared__ float sh[256];
    const int tid = threadIdx.x;
    float v = (tid < SEQL) ? y[b * SEQL + tid] : -INFINITY;
    sh[tid] = v; __syncthreads();
    for (int s = 128; s; s >>= 1) {
        if (tid < s) sh[tid] = fmaxf(sh[tid], sh[tid + s]);
        __syncthreads();
    }
    const float mx = sh[0]; __syncthreads();
    const float e = (tid < SEQL) ? __expf(v - mx) : 0.f;
    sh[tid] = e; __syncthreads();
    for (int s = 128; s; s >>= 1) {
        if (tid < s) sh[tid] += sh[tid + s];
        __syncthreads();
    }
    const float inv = 1.f / sh[0];
    if (tid < SEQL) g_p[b * SEQL + tid] = e * inv * 0.1f;
}

__global__ __launch_bounds__(256) void softmax_y2_kernel(
    const float* __restrict__ y2, float* __restrict__ y3)
{
    const int b = blockIdx.x;
    const int tid = threadIdx.x;
    __shared__ float sh[256];
    const float* src = y2 + (size_t)b * 2000;
    float mx = -INFINITY;
    for (int i = tid; i < 2000; i += 256) mx = fmaxf(mx, src[i]);
    sh[tid] = mx; __syncthreads();
    for (int s = 128; s; s >>= 1) {
        if (tid < s) sh[tid] = fmaxf(sh[tid], sh[tid + s]);
        __syncthreads();
    }
    mx = sh[0]; __syncthreads();
    float sum = 0.f;
    for (int i = tid; i < 2000; i += 256) sum += __expf(src[i] - mx);
    sh[tid] = sum; __syncthreads();
    for (int s = 128; s; s >>= 1) {
        if (tid < s) sh[tid] += sh[tid + s];
        __syncthreads();
    }
    const float inv = 1.f / sh[0];
    for (int i = tid; i < 2000; i += 256)
        y3[(size_t)b * 2000 + i] = __expf(src[i] - mx) * inv + g_p[b * SEQL + i / 10];
}

// ---------------- driver ------------------------------------------------------
extern "C" void kernel_launch(void* const* d_in, const int* in_sizes, int n_in,
                              void* d_out, int out_size) {
    (void)in_sizes; (void)n_in; (void)out_size;
    const float* x        = (const float*)d_in[0];
    const float* w_ih_l0  = (const float*)d_in[1];
    const float* w_hh_l0  = (const float*)d_in[2];
    const float* b_ih_l0  = (const float*)d_in[3];
    const float* b_hh_l0  = (const float*)d_in[4];
    const float* w_ih_l0r = (const float*)d_in[5];
    const float* w_hh_l0r = (const float*)d_in[6];
    const float* b_ih_l0r = (const float*)d_in[7];
    const float* b_hh_l0r = (const float*)d_in[8];
    const float* w_ih_l1  = (const float*)d_in[9];
    const float* w_hh_l1  = (const float*)d_in[10];
    const float* b_ih_l1  = (const float*)d_in[11];
    const float* b_hh_l1  = (const float*)d_in[12];
    const float* w_ih_l1r = (const float*)d_in[13];
    const float* w_hh_l1r = (const float*)d_in[14];
    const float* b_ih_l1r = (const float*)d_in[15];
    const float* b_hh_l1r = (const float*)d_in[16];
    const float* fc1_w    = (const float*)d_in[17];
    const float* fc1_b    = (const float*)d_in[18];
    const float* fc2_w    = (const float*)d_in[19];
    const float* fc2_b    = (const float*)d_in[20];

    float* y  = (float*)d_out;
    float* y2 = y + BL;
    float* y3 = y2 + BL * 10;

    static int configured = 0;
    if (!configured) {
        cudaFuncSetAttribute(gru_cluster, cudaFuncAttributeMaxDynamicSharedMemorySize,
                             GRU_SMEM_BYTES);
        configured = 1;
    }

    const dim3 ggrid(G3 / 128, BL / 128);

    gemm_xi<<<ggrid, 256>>>(0, x, w_ih_l0,  b_ih_l0,  0);
    gemm_xi<<<ggrid, 256>>>(0, x, w_ih_l0r, b_ih_l0r, 1);

    gru_cluster<<<128, 256, GRU_SMEM_BYTES>>>(w_hh_l0, w_hh_l0r, b_hh_l0, b_hh_l0r, 0);

    gemm_xi<<<ggrid, 256>>>(1, nullptr, w_ih_l1,  b_ih_l1,  0);
    gemm_xi<<<ggrid, 256>>>(1, nullptr, w_ih_l1r, b_ih_l1r, 1);

    gru_cluster<<<128, 256, GRU_SMEM_BYTES>>>(w_hh_l1, w_hh_l1r, b_hh_l1, b_hh_l1r, 1);

    fc_heads<<<BL, 128>>>(fc1_w, fc1_b, fc2_w, fc2_b, y, y2);
    softmax_y_kernel<<<BATCH, 256>>>(y);
    softmax_y2_kernel<<<BATCH, 256>>>(y2, y3);
}

// round 5
// speedup vs baseline: 2.0558x; 1.1008x over previous
#include <cuda_runtime.h>
#include <cuda_bf16.h>
#include <math.h>

// Problem constants
#define BATCH 256
#define SEQL  200
#define INF   512
#define HID   256
#define G3    768
#define BL    (BATCH*SEQL)   // 51200

// ---------------- scratch (device globals) -----------------------------------
__device__ float g_xi_f[(size_t)BL * G3];
__device__ float g_xi_r[(size_t)BL * G3];
__device__ float g_seq0[(size_t)BL * 512];
__device__ float g_seq1[(size_t)BL * 512];
__device__ float g_p[BL];

// ---------------- f32x2 packed helpers ---------------------------------------
__device__ __forceinline__ unsigned long long dup2(float x) {
    unsigned long long r;
    asm("mov.b64 %0, {%1, %1};" : "=l"(r) : "r"(__float_as_uint(x)));
    return r;
}
__device__ __forceinline__ void ffma2(unsigned long long& d, unsigned long long a,
                                      unsigned long long b) {
    asm("fma.rn.f32x2 %0, %1, %2, %0;" : "+l"(d) : "l"(a), "l"(b));
}
__device__ __forceinline__ unsigned long long add2(unsigned long long a,
                                                   unsigned long long b) {
    unsigned long long d;
    asm("add.rn.f32x2 %0, %1, %2;" : "=l"(d) : "l"(a), "l"(b));
    return d;
}
__device__ __forceinline__ float f2lo(unsigned long long v) {
    return __uint_as_float((unsigned)v);
}
__device__ __forceinline__ float f2hi(unsigned long long v) {
    return __uint_as_float((unsigned)(v >> 32));
}
__device__ __forceinline__ unsigned smem_u32(const void* p) {
    unsigned r;
    asm("{ .reg .u64 t; cvta.to.shared.u64 t, %1; cvt.u32.u64 %0, t; }"
        : "=r"(r) : "l"(p));
    return r;
}
__device__ __forceinline__ unsigned mapa_sh(unsigned addr, unsigned rank) {
    unsigned r;
    asm("mapa.shared::cluster.u32 %0, %1, %2;" : "=r"(r) : "r"(addr), "r"(rank));
    return r;
}
__device__ __forceinline__ void st_cluster_v2(unsigned addr, float x, float y) {
    asm volatile("st.shared::cluster.v2.f32 [%0], {%1, %2};"
                 :: "r"(addr), "f"(x), "f"(y) : "memory");
}
__device__ __forceinline__ void cluster_arrive() {
    asm volatile("barrier.cluster.arrive.aligned;" ::: "memory");
}
__device__ __forceinline__ void cluster_wait() {
    asm volatile("barrier.cluster.wait.aligned;" ::: "memory");
}
__device__ __forceinline__ unsigned ctarank() {
    unsigned r;
    asm("mov.u32 %0, %%cluster_ctarank;" : "=r"(r));
    return r;
}
// fast, saturation-safe activations (~1e-7 rel err)
__device__ __forceinline__ float sigmoid_f(float x) {
    return __fdividef(1.f, 1.f + __expf(-x));
}
__device__ __forceinline__ float tanh_f(float x) {
    return 1.f - __fdividef(2.f, __expf(2.f * x) + 1.f);
}

// ---------------- GEMM: xi = A[M,512] @ W{f,r}[768,512]^T + b ------------------
// BM=128, BN=128, BK=8. Warp grid 2(m)x4(n): warp tile 64x32 -> 384B unique smem
// per warp per k (vs 576 for 16x128). A uses m-swizzle phys = m + (m>>5)*4 so
// both LDS.128 A-fragment reads and STS are bank-conflict-free. fwd+rev fused:
// blockIdx.x in [0,12), rev = bx >= 6.
#define AST 140
#define BST 132
__global__ __launch_bounds__(256) void gemm_xi(
    int srcsel, const float* __restrict__ x,
    const float* __restrict__ Wf, const float* __restrict__ bf,
    const float* __restrict__ Wr, const float* __restrict__ br_)
{
    const float* A = srcsel ? g_seq0 : x;
    const int bx = blockIdx.x;
    const int rev = bx >= 6;
    const float* W    = rev ? Wr  : Wf;
    const float* bias = rev ? br_ : bf;
    float* C          = rev ? g_xi_r : g_xi_f;
    const int n0 = (rev ? bx - 6 : bx) * 128;
    const int m0 = blockIdx.y * 128;

    __shared__ float As[2][8][AST];
    __shared__ float Bs[2][8][BST];

    const int tid = threadIdx.x;
    const int wid = tid >> 5, lane = tid & 31;
    const int wm = wid >> 2, wn = wid & 3;      // 2 x 4 warp grid
    const int tm = lane & 7, tn = lane >> 3;    // 8 x 4 threads in warp
    const int mb = wm * 64 + tm * 8;            // m base (block-local)
    const int pmb = mb + (mb >> 5) * 4;         // swizzled phys m base
    const int nb = wn * 32 + tn * 8;            // n base (block-local)

    const int lr = tid >> 1;                    // loader row 0..127
    const int plr = lr + (lr >> 5) * 4;         // swizzled for A
    const int lc = (tid & 1) * 4;               // loader k-offset 0 or 4

    unsigned long long acc[4][8];
#pragma unroll
    for (int p = 0; p < 4; p++)
#pragma unroll
        for (int j = 0; j < 8; j++) acc[p][j] = 0ull;

    const float* Aptr = A + (size_t)(m0 + lr) * INF + lc;
    const float* Wptr = W + (size_t)(n0 + lr) * INF + lc;

    float4 av = *(const float4*)(Aptr);
    float4 wv = *(const float4*)(Wptr);

    for (int t = 0; t < 64; t++) {
        const int buf = t & 1;
        As[buf][lc + 0][plr] = av.x; As[buf][lc + 1][plr] = av.y;
        As[buf][lc + 2][plr] = av.z; As[buf][lc + 3][plr] = av.w;
        Bs[buf][lc + 0][lr] = wv.x; Bs[buf][lc + 1][lr] = wv.y;
        Bs[buf][lc + 2][lr] = wv.z; Bs[buf][lc + 3][lr] = wv.w;
        __syncthreads();
        if (t < 63) {
            av = *(const float4*)(Aptr + (t + 1) * 8);
            wv = *(const float4*)(Wptr + (t + 1) * 8);
        }
#pragma unroll
        for (int k = 0; k < 8; k++) {
            const unsigned long long* ap =
                (const unsigned long long*)&As[buf][k][pmb];
            unsigned long long a2[4];
            a2[0] = ap[0]; a2[1] = ap[1]; a2[2] = ap[2]; a2[3] = ap[3];
            float4 b0 = *(const float4*)&Bs[buf][k][nb];
            float4 b1 = *(const float4*)&Bs[buf][k][nb + 4];
            unsigned long long bd[8];
            bd[0] = dup2(b0.x); bd[1] = dup2(b0.y); bd[2] = dup2(b0.z); bd[3] = dup2(b0.w);
            bd[4] = dup2(b1.x); bd[5] = dup2(b1.y); bd[6] = dup2(b1.z); bd[7] = dup2(b1.w);
#pragma unroll
            for (int p = 0; p < 4; p++)
#pragma unroll
                for (int j = 0; j < 8; j++) ffma2(acc[p][j], a2[p], bd[j]);
        }
    }

    float bb[8];
#pragma unroll
    for (int j = 0; j < 8; j++) bb[j] = bias[n0 + nb + j];

#pragma unroll
    for (int p = 0; p < 4; p++) {
        const int m = m0 + mb + 2 * p;
        float4 r0, r1, s0, s1;
        r0.x = f2lo(acc[p][0]) + bb[0]; r0.y = f2lo(acc[p][1]) + bb[1];
        r0.z = f2lo(acc[p][2]) + bb[2]; r0.w = f2lo(acc[p][3]) + bb[3];
        r1.x = f2lo(acc[p][4]) + bb[4]; r1.y = f2lo(acc[p][5]) + bb[5];
        r1.z = f2lo(acc[p][6]) + bb[6]; r1.w = f2lo(acc[p][7]) + bb[7];
        s0.x = f2hi(acc[p][0]) + bb[0]; s0.y = f2hi(acc[p][1]) + bb[1];
        s0.z = f2hi(acc[p][2]) + bb[2]; s0.w = f2hi(acc[p][3]) + bb[3];
        s1.x = f2hi(acc[p][4]) + bb[4]; s1.y = f2hi(acc[p][5]) + bb[5];
        s1.z = f2hi(acc[p][6]) + bb[6]; s1.w = f2hi(acc[p][7]) + bb[7];
        float* cp0 = C + (size_t)m * G3 + n0 + nb;
        float* cp1 = C + (size_t)(m + 1) * G3 + n0 + nb;
        *(float4*)cp0 = r0; *(float4*)(cp0 + 4) = r1;
        *(float4*)cp1 = s0; *(float4*)(cp1 + 4) = s1;
    }
}

// ---------------- cluster-persistent GRU recurrence ---------------------------
#define HSS 18
#define WS_FLOATS  (3 * 256 * 64)              // 196608 floats
#define HS_FLOATS  (256 * HSS)                 // 4608
#define RED_FLOATS (8 * 32 * 12)               // 3072
#define GRU_SMEM_BYTES ((WS_FLOATS + HS_FLOATS + RED_FLOATS) * 4)  // 227328 B

__global__ void __launch_bounds__(256, 1) __cluster_dims__(4, 1, 1)
gru_cluster(const float* __restrict__ whh_f, const float* __restrict__ whh_r,
            const float* __restrict__ bhh_f, const float* __restrict__ bhh_r,
            int layer)
{
    extern __shared__ float sm[];
    float* ws  = sm;                            // [3*256 (g,k)][64 hloc]
    float* hs  = sm + WS_FLOATS;                // [256 k][HSS] (16 b used)
    float* red = sm + WS_FLOATS + HS_FLOATS;    // [8 warp][32 lane][12]

    const unsigned rank = ctarank();
    const int cid = blockIdx.x >> 2;
    const int dir = cid >> 4;
    const int bg  = cid & 15;

    float* seq = layer ? g_seq1 : g_seq0;
    const float* xi  = dir ? g_xi_r : g_xi_f;
    const float* whh = dir ? whh_r : whh_f;
    const float* bhh = dir ? bhh_r : bhh_f;
    const int zoff = dir * HID;

    const int tid  = threadIdx.x;
    const int w    = tid >> 5;
    const int lane = tid & 31;
    const int hh    = w & 1;
    const int boct  = (w >> 1) & 1;
    const int khalf = w >> 2;
    const int k0 = khalf * 128;
    const int jb = khalf * 4;

    if (tid < 192) {
        const int g  = tid / 64;
        const int hl = tid % 64;
        const float* wrow = whh + (size_t)(g * HID + rank * 64 + hl) * HID;
        for (int k4 = 0; k4 < 256; k4 += 4) {
            float4 v = *(const float4*)(wrow + k4);
            ws[(g * 256 + k4 + 0) * 64 + hl] = v.x;
            ws[(g * 256 + k4 + 1) * 64 + hl] = v.y;
            ws[(g * 256 + k4 + 2) * 64 + hl] = v.z;
            ws[(g * 256 + k4 + 3) * 64 + hl] = v.w;
        }
    }
    for (int i = tid; i < HS_FLOATS; i += 256) hs[i] = 0.f;
    __syncthreads();

    const int hglob = rank * 64 + hh * 32 + lane;
    const float br = bhh[hglob], bz = bhh[HID + hglob], bn = bhh[2 * HID + hglob];
    const unsigned hs_dst_u32 =
        smem_u32(hs) + (unsigned)((hglob * HSS + boct * 8 + jb) * 4);
    unsigned hs_dst_r[4];
#pragma unroll
    for (unsigned r = 0; r < 4; r++) hs_dst_r[r] = mapa_sh(hs_dst_u32, r);

    float xig[3][4];
#pragma unroll
    for (int j = 0; j < 4; j++) {
        const int b = bg * 16 + boct * 8 + jb + j;
        const int t0 = dir ? (SEQL - 1) : 0;
        const float* xp = xi + ((size_t)b * SEQL + t0) * G3 + hglob;
#pragma unroll
        for (int g = 0; g < 3; g++) xig[g][j] = __ldg(xp + g * HID);
    }

    for (int s = 0; s < SEQL; s++) {
        const int t = dir ? (SEQL - 1 - s) : s;

        unsigned long long acc[3][4];
#pragma unroll
        for (int g = 0; g < 3; g++)
#pragma unroll
            for (int p = 0; p < 4; p++) acc[g][p] = 0ull;

#pragma unroll 4
        for (int k = k0; k < k0 + 128; k++) {
            unsigned long long h2[4];
#pragma unroll
            for (int p = 0; p < 4; p++)
                h2[p] = *(const unsigned long long*)&hs[k * HSS + boct * 8 + 2 * p];
#pragma unroll
            for (int g = 0; g < 3; g++) {
                const unsigned long long wd =
                    dup2(ws[(g * 256 + k) * 64 + hh * 32 + lane]);
#pragma unroll
                for (int p = 0; p < 4; p++) ffma2(acc[g][p], h2[p], wd);
            }
        }

        float hp[4];
#pragma unroll
        for (int j = 0; j < 4; j++) hp[j] = hs[hglob * HSS + boct * 8 + jb + j];

        cluster_arrive();

        {
            float* myred = &red[(w * 32 + lane) * 12];
            const int pe = khalf ? 0 : 2;
#pragma unroll
            for (int g = 0; g < 3; g++) {
                *(unsigned long long*)&myred[(g * 2 + 0) * 2] = acc[g][pe + 0];
                *(unsigned long long*)&myred[(g * 2 + 1) * 2] = acc[g][pe + 1];
            }
        }
        __syncthreads();
        {
            const int peer = khalf ? (w - 4) : (w + 4);
            const float* pr = &red[(peer * 32 + lane) * 12];
            const int pk = khalf ? 2 : 0;
#pragma unroll
            for (int g = 0; g < 3; g++) {
                acc[g][pk + 0] = add2(acc[g][pk + 0],
                                      *(const unsigned long long*)&pr[(g * 2 + 0) * 2]);
                acc[g][pk + 1] = add2(acc[g][pk + 1],
                                      *(const unsigned long long*)&pr[(g * 2 + 1) * 2]);
            }
            if (pk) {
#pragma unroll
                for (int g = 0; g < 3; g++) { acc[g][0] = acc[g][2]; acc[g][1] = acc[g][3]; }
            }
        }

        float hnew[4];
#pragma unroll
        for (int p = 0; p < 2; p++) {
#pragma unroll
            for (int half = 0; half < 2; half++) {
                const int j = 2 * p + half;
                const float gr = (half ? f2hi(acc[0][p]) : f2lo(acc[0][p])) + br;
                const float gz = (half ? f2hi(acc[1][p]) : f2lo(acc[1][p])) + bz;
                const float gn = (half ? f2hi(acc[2][p]) : f2lo(acc[2][p])) + bn;
                const float rg = sigmoid_f(xig[0][j] + gr);
                const float zg = sigmoid_f(xig[1][j] + gz);
                const float ng = tanh_f(xig[2][j] + rg * gn);
                hnew[j] = (1.f - zg) * ng + zg * hp[j];
                const int b = bg * 16 + boct * 8 + jb + j;
                seq[((size_t)b * SEQL + t) * 512 + zoff + hglob] = hnew[j];
            }
        }

        cluster_wait();

#pragma unroll
        for (unsigned r = 0; r < 4; r++) {
            st_cluster_v2(hs_dst_r[r] + 0, hnew[0], hnew[1]);
            st_cluster_v2(hs_dst_r[r] + 8, hnew[2], hnew[3]);
        }

        cluster_arrive();

        if (s + 1 < SEQL) {
            const int tn_ = dir ? (SEQL - 2 - s) : (s + 1);
#pragma unroll
            for (int j = 0; j < 4; j++) {
                const int b = bg * 16 + boct * 8 + jb + j;
                const float* xp = xi + ((size_t)b * SEQL + tn_) * G3 + hglob;
#pragma unroll
                for (int g = 0; g < 3; g++) xig[g][j] = __ldg(xp + g * HID);
            }
        }

        cluster_wait();
    }
}

// ---------------- heads ------------------------------------------------------
__global__ __launch_bounds__(128) void fc_heads(
    const float* __restrict__ fc1w, const float* __restrict__ fc1b,
    const float* __restrict__ fc2w, const float* __restrict__ fc2b,
    float* __restrict__ y, float* __restrict__ y2)
{
    const int bt = blockIdx.x;
    __shared__ float row[512];
    const int tid = threadIdx.x;
    const float* src = g_seq1 + (size_t)bt * 512;
    for (int i = tid; i < 512; i += 128) row[i] = src[i];
    __syncthreads();
    const int warp = tid >> 5, lane = tid & 31;
    for (int j = warp; j < 11; j += 4) {
        const float* w = (j == 10) ? fc1w : fc2w + (size_t)j * 512;
        float s = 0.f;
#pragma unroll
        for (int i = 0; i < 16; i++) s += row[lane + 32 * i] * w[lane + 32 * i];
#pragma unroll
        for (int off = 16; off; off >>= 1) s += __shfl_xor_sync(0xffffffffu, s, off);
        if (lane == 0) {
            if (j == 10) y[bt] = s + fc1b[0];
            else         y2[(size_t)bt * 10 + j] = s + fc2b[j];
        }
    }
}

__global__ __launch_bounds__(256) void softmax_y_kernel(const float* __restrict__ y) {
    const int b = blockIdx.x;
    __shared__ float sh[256];
    const int tid = threadIdx.x;
    float v = (tid < SEQL) ? y[b * SEQL + tid] : -INFINITY;
    sh[tid] = v; __syncthreads();
    for (int s = 128; s; s >>= 1) {
        if (tid < s) sh[tid] = fmaxf(sh[tid], sh[tid + s]);
        __syncthreads();
    }
    const float mx = sh[0]; __syncthreads();
    const float e = (tid < SEQL) ? __expf(v - mx) : 0.f;
    sh[tid] = e; __syncthreads();
    for (int s = 128; s; s >>= 1) {
        if (tid < s) sh[tid] += sh[tid + s];
        __syncthreads();
    }
    const float inv = 1.f / sh[0];
    if (tid < SEQL) g_p[b * SEQL + tid] = e * inv * 0.1f;
}

__global__ __launch_bounds__(256) void softmax_y2_kernel(
    const float* __restrict__ y2, float* __restrict__ y3)
{
    const int b = blockIdx.x;
    const int tid = threadIdx.x;
    __shared__ float sh[256];
    const float* src = y2 + (size_t)b * 2000;
    float mx = -INFINITY;
    for (int i = tid; i < 2000; i += 256) mx = fmaxf(mx, src[i]);
    sh[tid] = mx; __syncthreads();
    for (int s = 128; s; s >>= 1) {
        if (tid < s) sh[tid] = fmaxf(sh[tid], sh[tid + s]);
        __syncthreads();
    }
    mx = sh[0]; __syncthreads();
    float sum = 0.f;
    for (int i = tid; i < 2000; i += 256) sum += __expf(src[i] - mx);
    sh[tid] = sum; __syncthreads();
    for (int s = 128; s; s >>= 1) {
        if (tid < s) sh[tid] += sh[tid + s];
        __syncthreads();
    }
    const float inv = 1.f / sh[0];
    for (int i = tid; i < 2000; i += 256)
        y3[(size_t)b * 2000 + i] = __expf(src[i] - mx) * inv + g_p[b * SEQL + i / 10];
}

// ---------------- driver ------------------------------------------------------
extern "C" void kernel_launch(void* const* d_in, const int* in_sizes, int n_in,
                              void* d_out, int out_size) {
    (void)in_sizes; (void)n_in; (void)out_size;
    const float* x        = (const float*)d_in[0];
    const float* w_ih_l0  = (const float*)d_in[1];
    const float* w_hh_l0  = (const float*)d_in[2];
    const float* b_ih_l0  = (const float*)d_in[3];
    const float* b_hh_l0  = (const float*)d_in[4];
    const float* w_ih_l0r = (const float*)d_in[5];
    const float* w_hh_l0r = (const float*)d_in[6];
    const float* b_ih_l0r = (const float*)d_in[7];
    const float* b_hh_l0r = (const float*)d_in[8];
    const float* w_ih_l1  = (const float*)d_in[9];
    const float* w_hh_l1  = (const float*)d_in[10];
    const float* b_ih_l1  = (const float*)d_in[11];
    const float* b_hh_l1  = (const float*)d_in[12];
    const float* w_ih_l1r = (const float*)d_in[13];
    const float* w_hh_l1r = (const float*)d_in[14];
    const float* b_ih_l1r = (const float*)d_in[15];
    const float* b_hh_l1r = (const float*)d_in[16];
    const float* fc1_w    = (const float*)d_in[17];
    const float* fc1_b    = (const float*)d_in[18];
    const float* fc2_w    = (const float*)d_in[19];
    const float* fc2_b    = (const float*)d_in[20];

    float* y  = (float*)d_out;
    float* y2 = y + BL;
    float* y3 = y2 + BL * 10;

    static int configured = 0;
    if (!configured) {
        cudaFuncSetAttribute(gru_cluster, cudaFuncAttributeMaxDynamicSharedMemorySize,
                             GRU_SMEM_BYTES);
        configured = 1;
    }

    const dim3 ggrid(12, BL / 128);   // fwd (bx<6) + rev (bx>=6) fused

    gemm_xi<<<ggrid, 256>>>(0, x, w_ih_l0, b_ih_l0, w_ih_l0r, b_ih_l0r);

    gru_cluster<<<128, 256, GRU_SMEM_BYTES>>>(w_hh_l0, w_hh_l0r, b_hh_l0, b_hh_l0r, 0);

    gemm_xi<<<ggrid, 256>>>(1, nullptr, w_ih_l1, b_ih_l1, w_ih_l1r, b_ih_l1r);

    gru_cluster<<<128, 256, GRU_SMEM_BYTES>>>(w_hh_l1, w_hh_l1r, b_hh_l1, b_hh_l1r, 1);

    fc_heads<<<BL, 128>>>(fc1_w, fc1_b, fc2_w, fc2_b, y, y2);
    softmax_y_kernel<<<BATCH, 256>>>(y);
    softmax_y2_kernel<<<BATCH, 256>>>(y2, y3);
}

// round 6
// speedup vs baseline: 2.0854x; 1.0144x over previous
#include <cuda_runtime.h>
#include <cuda_bf16.h>
#include <math.h>

// Problem constants
#define BATCH 256
#define SEQL  200
#define INF   512
#define HID   256
#define G3    768
#define BL    (BATCH*SEQL)   // 51200

// ---------------- scratch (device globals) -----------------------------------
__device__ float g_xi_f[(size_t)BL * G3];
__device__ float g_xi_r[(size_t)BL * G3];
__device__ float g_seq0[(size_t)BL * 512];
__device__ float g_seq1[(size_t)BL * 512];
__device__ float g_p[BL];

// ---------------- f32x2 packed helpers ---------------------------------------
__device__ __forceinline__ unsigned long long dup2(float x) {
    unsigned long long r;
    asm("mov.b64 %0, {%1, %1};" : "=l"(r) : "r"(__float_as_uint(x)));
    return r;
}
__device__ __forceinline__ void ffma2(unsigned long long& d, unsigned long long a,
                                      unsigned long long b) {
    asm("fma.rn.f32x2 %0, %1, %2, %0;" : "+l"(d) : "l"(a), "l"(b));
}
__device__ __forceinline__ float f2lo(unsigned long long v) {
    return __uint_as_float((unsigned)v);
}
__device__ __forceinline__ float f2hi(unsigned long long v) {
    return __uint_as_float((unsigned)(v >> 32));
}
__device__ __forceinline__ unsigned smem_u32(const void* p) {
    unsigned r;
    asm("{ .reg .u64 t; cvta.to.shared.u64 t, %1; cvt.u32.u64 %0, t; }"
        : "=r"(r) : "l"(p));
    return r;
}
__device__ __forceinline__ unsigned mapa_sh(unsigned addr, unsigned rank) {
    unsigned r;
    asm("mapa.shared::cluster.u32 %0, %1, %2;" : "=r"(r) : "r"(addr), "r"(rank));
    return r;
}
__device__ __forceinline__ void st_cluster_v2(unsigned addr, float x, float y) {
    asm volatile("st.shared::cluster.v2.f32 [%0], {%1, %2};"
                 :: "r"(addr), "f"(x), "f"(y) : "memory");
}
__device__ __forceinline__ void cluster_arrive() {
    asm volatile("barrier.cluster.arrive.aligned;" ::: "memory");
}
__device__ __forceinline__ void cluster_wait() {
    asm volatile("barrier.cluster.wait.aligned;" ::: "memory");
}
__device__ __forceinline__ void cluster_sync_full() {
    cluster_arrive(); cluster_wait();
}
__device__ __forceinline__ unsigned ctarank() {
    unsigned r;
    asm("mov.u32 %0, %%cluster_ctarank;" : "=r"(r));
    return r;
}
// fast, saturation-safe activations (~1e-7 rel err)
__device__ __forceinline__ float sigmoid_f(float x) {
    return __fdividef(1.f, 1.f + __expf(-x));
}
__device__ __forceinline__ float tanh_f(float x) {
    return 1.f - __fdividef(2.f, __expf(2.f * x) + 1.f);
}

// ---------------- GEMM: xi = A[M,512] @ W{f,r}[768,512]^T + b ------------------
// BM=128, BN=128, BK=8, warp grid 2(m)x4(n), m-swizzled A smem; fwd+rev fused.
#define AST 140
#define BST 132
__global__ __launch_bounds__(256) void gemm_xi(
    int srcsel, const float* __restrict__ x,
    const float* __restrict__ Wf, const float* __restrict__ bf,
    const float* __restrict__ Wr, const float* __restrict__ br_)
{
    const float* A = srcsel ? g_seq0 : x;
    const int bx = blockIdx.x;
    const int rev = bx >= 6;
    const float* W    = rev ? Wr  : Wf;
    const float* bias = rev ? br_ : bf;
    float* C          = rev ? g_xi_r : g_xi_f;
    const int n0 = (rev ? bx - 6 : bx) * 128;
    const int m0 = blockIdx.y * 128;

    __shared__ float As[2][8][AST];
    __shared__ float Bs[2][8][BST];

    const int tid = threadIdx.x;
    const int wid = tid >> 5, lane = tid & 31;
    const int wm = wid >> 2, wn = wid & 3;
    const int tm = lane & 7, tn = lane >> 3;
    const int mb = wm * 64 + tm * 8;
    const int pmb = mb + (mb >> 5) * 4;
    const int nb = wn * 32 + tn * 8;

    const int lr = tid >> 1;
    const int plr = lr + (lr >> 5) * 4;
    const int lc = (tid & 1) * 4;

    unsigned long long acc[4][8];
#pragma unroll
    for (int p = 0; p < 4; p++)
#pragma unroll
        for (int j = 0; j < 8; j++) acc[p][j] = 0ull;

    const float* Aptr = A + (size_t)(m0 + lr) * INF + lc;
    const float* Wptr = W + (size_t)(n0 + lr) * INF + lc;

    float4 av = *(const float4*)(Aptr);
    float4 wv = *(const float4*)(Wptr);

    for (int t = 0; t < 64; t++) {
        const int buf = t & 1;
        As[buf][lc + 0][plr] = av.x; As[buf][lc + 1][plr] = av.y;
        As[buf][lc + 2][plr] = av.z; As[buf][lc + 3][plr] = av.w;
        Bs[buf][lc + 0][lr] = wv.x; Bs[buf][lc + 1][lr] = wv.y;
        Bs[buf][lc + 2][lr] = wv.z; Bs[buf][lc + 3][lr] = wv.w;
        __syncthreads();
        if (t < 63) {
            av = *(const float4*)(Aptr + (t + 1) * 8);
            wv = *(const float4*)(Wptr + (t + 1) * 8);
        }
#pragma unroll
        for (int k = 0; k < 8; k++) {
            const unsigned long long* ap =
                (const unsigned long long*)&As[buf][k][pmb];
            unsigned long long a2[4];
            a2[0] = ap[0]; a2[1] = ap[1]; a2[2] = ap[2]; a2[3] = ap[3];
            float4 b0 = *(const float4*)&Bs[buf][k][nb];
            float4 b1 = *(const float4*)&Bs[buf][k][nb + 4];
            unsigned long long bd[8];
            bd[0] = dup2(b0.x); bd[1] = dup2(b0.y); bd[2] = dup2(b0.z); bd[3] = dup2(b0.w);
            bd[4] = dup2(b1.x); bd[5] = dup2(b1.y); bd[6] = dup2(b1.z); bd[7] = dup2(b1.w);
#pragma unroll
            for (int p = 0; p < 4; p++)
#pragma unroll
                for (int j = 0; j < 8; j++) ffma2(acc[p][j], a2[p], bd[j]);
        }
    }

    float bb[8];
#pragma unroll
    for (int j = 0; j < 8; j++) bb[j] = bias[n0 + nb + j];

#pragma unroll
    for (int p = 0; p < 4; p++) {
        const int m = m0 + mb + 2 * p;
        float4 r0, r1, s0, s1;
        r0.x = f2lo(acc[p][0]) + bb[0]; r0.y = f2lo(acc[p][1]) + bb[1];
        r0.z = f2lo(acc[p][2]) + bb[2]; r0.w = f2lo(acc[p][3]) + bb[3];
        r1.x = f2lo(acc[p][4]) + bb[4]; r1.y = f2lo(acc[p][5]) + bb[5];
        r1.z = f2lo(acc[p][6]) + bb[6]; r1.w = f2lo(acc[p][7]) + bb[7];
        s0.x = f2hi(acc[p][0]) + bb[0]; s0.y = f2hi(acc[p][1]) + bb[1];
        s0.z = f2hi(acc[p][2]) + bb[2]; s0.w = f2hi(acc[p][3]) + bb[3];
        s1.x = f2hi(acc[p][4]) + bb[4]; s1.y = f2hi(acc[p][5]) + bb[5];
        s1.z = f2hi(acc[p][6]) + bb[6]; s1.w = f2hi(acc[p][7]) + bb[7];
        float* cp0 = C + (size_t)m * G3 + n0 + nb;
        float* cp1 = C + (size_t)(m + 1) * G3 + n0 + nb;
        *(float4*)cp0 = r0; *(float4*)(cp0 + 4) = r1;
        *(float4*)cp1 = s0; *(float4*)(cp1 + 4) = s1;
    }
}

// ---------------- cluster-persistent GRU recurrence ---------------------------
// 32 clusters x 4 CTAs. CTA rank owns 64 h rows x 3 gates (192KB weights, k-pair
// packed). Warp = (h-quarter, b-half): full k per warp -> no cross-warp reduce.
// hs double-buffered [2][256 k][16]: one cluster barrier per step; handoff via
// st.shared::cluster.
#define HSS 16
#define WS_FLOATS  (3 * 128 * 128)             // 49152 floats (k-pair packed)
#define HSBUF_FLOATS (256 * HSS)               // 4096
#define HSBUF_BYTES  (HSBUF_FLOATS * 4)        // 16384
#define GRU_SMEM_BYTES ((WS_FLOATS + 2 * HSBUF_FLOATS) * 4)  // 229376 B

__global__ void __launch_bounds__(256, 1) __cluster_dims__(4, 1, 1)
gru_cluster(const float* __restrict__ whh_f, const float* __restrict__ whh_r,
            const float* __restrict__ bhh_f, const float* __restrict__ bhh_r,
            int layer)
{
    extern __shared__ float sm[];
    float* ws = sm;                       // [(g*128+kk)*128 + h*2 + par]
    float* hs = sm + WS_FLOATS;           // [2][256 k][HSS]

    const unsigned rank = ctarank();
    const int cid = blockIdx.x >> 2;
    const int dir = cid >> 4;
    const int bg  = cid & 15;

    float* seq = layer ? g_seq1 : g_seq0;
    const float* xi  = dir ? g_xi_r : g_xi_f;
    const float* whh = dir ? whh_r : whh_f;
    const float* bhh = dir ? bhh_r : bhh_f;
    const int zoff = dir * HID;

    const int tid  = threadIdx.x;
    const int w    = tid >> 5;
    const int lane = tid & 31;
    const int hq    = w & 3;          // h quarter (16 h)
    const int bhalf = w >> 2;         // batch half (8 b)
    const int hl    = lane & 15;      // h within quarter
    const int bpair = lane >> 4;      // which 4-batch group
    const int bb    = bhalf * 8 + bpair * 4;   // local batch base (4 batches)
    const int hx2   = (hq * 16 + hl) * 2;      // ws h index (k-pair layout)

    // ---- stage weights, k-pair packed: ws[(g*128+kk)*128 + h*2 + par] ----
    {
        const int h = tid >> 2;              // 0..63
        const int kb = (tid & 3) * 32;       // kk base
        for (int g = 0; g < 3; g++) {
            const float* wrow = whh + (size_t)(g * HID + rank * 64 + h) * HID;
#pragma unroll 4
            for (int kk = kb; kk < kb + 32; kk++) {
                float2 v = *(const float2*)(wrow + 2 * kk);
                *(float2*)&ws[(g * 128 + kk) * 128 + h * 2] = v;
            }
        }
    }
    // zero hs buf0 (h0 = 0); buf1 fully written at step 0
    for (int i = tid; i < HSBUF_FLOATS; i += 256) hs[i] = 0.f;
    __syncthreads();
    cluster_sync_full();   // peers' hs[1] ready to receive step-0 writes

    const int hglob = rank * 64 + hq * 16 + hl;
    const float br = bhh[hglob], bz = bhh[HID + hglob], bn = bhh[2 * HID + hglob];
    unsigned dst_r[4];
    {
        const unsigned base =
            smem_u32(hs) + (unsigned)((hglob * HSS + bb) * 4);
#pragma unroll
        for (unsigned r = 0; r < 4; r++) dst_r[r] = mapa_sh(base, r);
    }

    // initial xi prefetch
    float xig[3][4];
#pragma unroll
    for (int j = 0; j < 4; j++) {
        const int b = bg * 16 + bb + j;
        const int t0 = dir ? (SEQL - 1) : 0;
        const float* xp = xi + ((size_t)b * SEQL + t0) * G3 + hglob;
#pragma unroll
        for (int g = 0; g < 3; g++) xig[g][j] = __ldg(xp + g * HID);
    }

    for (int s = 0; s < SEQL; s++) {
        const int t = dir ? (SEQL - 1 - s) : s;
        const int par = s & 1;
        const float* hsr = hs + par * HSBUF_FLOATS;

        unsigned long long acc[3][2];
#pragma unroll
        for (int g = 0; g < 3; g++) { acc[g][0] = 0ull; acc[g][1] = 0ull; }

#pragma unroll 4
        for (int kk = 0; kk < 128; kk++) {
            const ulonglong2 ha =
                *(const ulonglong2*)&hsr[(2 * kk) * HSS + bb];
            const ulonglong2 hb =
                *(const ulonglong2*)&hsr[(2 * kk + 1) * HSS + bb];
#pragma unroll
            for (int g = 0; g < 3; g++) {
                const float2 wv = *(const float2*)&ws[(g * 128 + kk) * 128 + hx2];
                const unsigned long long w0 = dup2(wv.x);
                const unsigned long long w1 = dup2(wv.y);
                ffma2(acc[g][0], ha.x, w0);
                ffma2(acc[g][1], ha.y, w0);
                ffma2(acc[g][0], hb.x, w1);
                ffma2(acc[g][1], hb.y, w1);
            }
        }

        // h_prev for this thread's 4 batches
        const float4 hp = *(const float4*)&hsr[hglob * HSS + bb];

        // ---- epilogue ----
        float hnew[4];
        {
            const float hpj[4] = {hp.x, hp.y, hp.z, hp.w};
#pragma unroll
            for (int p = 0; p < 2; p++) {
#pragma unroll
                for (int half = 0; half < 2; half++) {
                    const int j = 2 * p + half;
                    const float gr = (half ? f2hi(acc[0][p]) : f2lo(acc[0][p])) + br;
                    const float gz = (half ? f2hi(acc[1][p]) : f2lo(acc[1][p])) + bz;
                    const float gn = (half ? f2hi(acc[2][p]) : f2lo(acc[2][p])) + bn;
                    const float rg = sigmoid_f(xig[0][j] + gr);
                    const float zg = sigmoid_f(xig[1][j] + gz);
                    const float ng = tanh_f(xig[2][j] + rg * gn);
                    hnew[j] = (1.f - zg) * ng + zg * hpj[j];
                    const int b = bg * 16 + bb + j;
                    seq[((size_t)b * SEQL + t) * 512 + zoff + hglob] = hnew[j];
                }
            }
        }

        // ---- distribute h_new into buffer par^1 of all 4 ranks ----
        const unsigned boff = (unsigned)((par ^ 1) * HSBUF_BYTES);
#pragma unroll
        for (unsigned r = 0; r < 4; r++) {
            st_cluster_v2(dst_r[r] + boff + 0, hnew[0], hnew[1]);
            st_cluster_v2(dst_r[r] + boff + 8, hnew[2], hnew[3]);
        }

        cluster_arrive();

        if (s + 1 < SEQL) {
            const int tn_ = dir ? (SEQL - 2 - s) : (s + 1);
#pragma unroll
            for (int j = 0; j < 4; j++) {
                const int b = bg * 16 + bb + j;
                const float* xp = xi + ((size_t)b * SEQL + tn_) * G3 + hglob;
#pragma unroll
                for (int g = 0; g < 3; g++) xig[g][j] = __ldg(xp + g * HID);
            }
        }

        cluster_wait();   // all ranks' writes to buf par^1 visible
    }
}

// ---------------- heads ------------------------------------------------------
__global__ __launch_bounds__(128) void fc_heads(
    const float* __restrict__ fc1w, const float* __restrict__ fc1b,
    const float* __restrict__ fc2w, const float* __restrict__ fc2b,
    float* __restrict__ y, float* __restrict__ y2)
{
    const int bt = blockIdx.x;
    __shared__ float row[512];
    const int tid = threadIdx.x;
    const float* src = g_seq1 + (size_t)bt * 512;
    for (int i = tid; i < 512; i += 128) row[i] = src[i];
    __syncthreads();
    const int warp = tid >> 5, lane = tid & 31;
    for (int j = warp; j < 11; j += 4) {
        const float* w = (j == 10) ? fc1w : fc2w + (size_t)j * 512;
        float s = 0.f;
#pragma unroll
        for (int i = 0; i < 16; i++) s += row[lane + 32 * i] * w[lane + 32 * i];
#pragma unroll
        for (int off = 16; off; off >>= 1) s += __shfl_xor_sync(0xffffffffu, s, off);
        if (lane == 0) {
            if (j == 10) y[bt] = s + fc1b[0];
            else         y2[(size_t)bt * 10 + j] = s + fc2b[j];
        }
    }
}

__global__ __launch_bounds__(256) void softmax_y_kernel(const float* __restrict__ y) {
    const int b = blockIdx.x;
    __shared__ float sh[256];
    const int tid = threadIdx.x;
    float v = (tid < SEQL) ? y[b * SEQL + tid] : -INFINITY;
    sh[tid] = v; __syncthreads();
    for (int s = 128; s; s >>= 1) {
        if (tid < s) sh[tid] = fmaxf(sh[tid], sh[tid + s]);
        __syncthreads();
    }
    const float mx = sh[0]; __syncthreads();
    const float e = (tid < SEQL) ? __expf(v - mx) : 0.f;
    sh[tid] = e; __syncthreads();
    for (int s = 128; s; s >>= 1) {
        if (tid < s) sh[tid] += sh[tid + s];
        __syncthreads();
    }
    const float inv = 1.f / sh[0];
    if (tid < SEQL) g_p[b * SEQL + tid] = e * inv * 0.1f;
}

__global__ __launch_bounds__(256) void softmax_y2_kernel(
    const float* __restrict__ y2, float* __restrict__ y3)
{
    const int b = blockIdx.x;
    const int tid = threadIdx.x;
    __shared__ float sh[256];
    const float* src = y2 + (size_t)b * 2000;
    float mx = -INFINITY;
    for (int i = tid; i < 2000; i += 256) mx = fmaxf(mx, src[i]);
    sh[tid] = mx; __syncthreads();
    for (int s = 128; s; s >>= 1) {
        if (tid < s) sh[tid] = fmaxf(sh[tid], sh[tid + s]);
        __syncthreads();
    }
    mx = sh[0]; __syncthreads();
    float sum = 0.f;
    for (int i = tid; i < 2000; i += 256) sum += __expf(src[i] - mx);
    sh[tid] = sum; __syncthreads();
    for (int s = 128; s; s >>= 1) {
        if (tid < s) sh[tid] += sh[tid + s];
        __syncthreads();
    }
    const float inv = 1.f / sh[0];
    for (int i = tid; i < 2000; i += 256)
        y3[(size_t)b * 2000 + i] = __expf(src[i] - mx) * inv + g_p[b * SEQL + i / 10];
}

// ---------------- driver ------------------------------------------------------
extern "C" void kernel_launch(void* const* d_in, const int* in_sizes, int n_in,
                              void* d_out, int out_size) {
    (void)in_sizes; (void)n_in; (void)out_size;
    const float* x        = (const float*)d_in[0];
    const float* w_ih_l0  = (const float*)d_in[1];
    const float* w_hh_l0  = (const float*)d_in[2];
    const float* b_ih_l0  = (const float*)d_in[3];
    const float* b_hh_l0  = (const float*)d_in[4];
    const float* w_ih_l0r = (const float*)d_in[5];
    const float* w_hh_l0r = (const float*)d_in[6];
    const float* b_ih_l0r = (const float*)d_in[7];
    const float* b_hh_l0r = (const float*)d_in[8];
    const float* w_ih_l1  = (const float*)d_in[9];
    const float* w_hh_l1  = (const float*)d_in[10];
    const float* b_ih_l1  = (const float*)d_in[11];
    const float* b_hh_l1  = (const float*)d_in[12];
    const float* w_ih_l1r = (const float*)d_in[13];
    const float* w_hh_l1r = (const float*)d_in[14];
    const float* b_ih_l1r = (const float*)d_in[15];
    const float* b_hh_l1r = (const float*)d_in[16];
    const float* fc1_w    = (const float*)d_in[17];
    const float* fc1_b    = (const float*)d_in[18];
    const float* fc2_w    = (const float*)d_in[19];
    const float* fc2_b    = (const float*)d_in[20];

    float* y  = (float*)d_out;
    float* y2 = y + BL;
    float* y3 = y2 + BL * 10;

    static int configured = 0;
    if (!configured) {
        cudaFuncSetAttribute(gru_cluster, cudaFuncAttributeMaxDynamicSharedMemorySize,
                             GRU_SMEM_BYTES);
        configured = 1;
    }

    const dim3 ggrid(12, BL / 128);   // fwd (bx<6) + rev (bx>=6) fused

    gemm_xi<<<ggrid, 256>>>(0, x, w_ih_l0, b_ih_l0, w_ih_l0r, b_ih_l0r);

    gru_cluster<<<128, 256, GRU_SMEM_BYTES>>>(w_hh_l0, w_hh_l0r, b_hh_l0, b_hh_l0r, 0);

    gemm_xi<<<ggrid, 256>>>(1, nullptr, w_ih_l1, b_ih_l1, w_ih_l1r, b_ih_l1r);

    gru_cluster<<<128, 256, GRU_SMEM_BYTES>>>(w_hh_l1, w_hh_l1r, b_hh_l1, b_hh_l1r, 1);

    fc_heads<<<BL, 128>>>(fc1_w, fc1_b, fc2_w, fc2_b, y, y2);
    softmax_y_kernel<<<BATCH, 256>>>(y);
    softmax_y2_kernel<<<BATCH, 256>>>(y2, y3);
}

// round 8
// speedup vs baseline: 2.2171x; 1.0631x over previous
#include <cuda_runtime.h>
#include <cuda_bf16.h>
#include <math.h>

// Problem constants
#define BATCH 256
#define SEQL  200
#define INF   512
#define HID   256
#define G3    768
#define BL    (BATCH*SEQL)   // 51200

// ---------------- scratch (device globals) -----------------------------------
__device__ float g_xi_f[(size_t)BL * G3];
__device__ float g_xi_r[(size_t)BL * G3];
__device__ float g_seq0[(size_t)BL * 512];
__device__ float g_seq1[(size_t)BL * 512];
__device__ float g_p[BL];
__device__ __nv_bfloat16 g_a2[(size_t)BL * 1024];      // A split: [row][hi(512)|lo(512)]
__device__ __nv_bfloat16 g_w2[2ull * G3 * 1024];       // W split per dir

// ---------------- f32x2 packed helpers ---------------------------------------
__device__ __forceinline__ unsigned long long dup2(float x) {
    unsigned long long r;
    asm("mov.b64 %0, {%1, %1};" : "=l"(r) : "r"(__float_as_uint(x)));
    return r;
}
__device__ __forceinline__ void ffma2(unsigned long long& d, unsigned long long a,
                                      unsigned long long b) {
    asm("fma.rn.f32x2 %0, %1, %2, %0;" : "+l"(d) : "l"(a), "l"(b));
}
__device__ __forceinline__ float f2lo(unsigned long long v) {
    return __uint_as_float((unsigned)v);
}
__device__ __forceinline__ float f2hi(unsigned long long v) {
    return __uint_as_float((unsigned)(v >> 32));
}
__device__ __forceinline__ unsigned smem_u32(const void* p) {
    unsigned r;
    asm("{ .reg .u64 t; cvta.to.shared.u64 t, %1; cvt.u32.u64 %0, t; }"
        : "=r"(r) : "l"(p));
    return r;
}
__device__ __forceinline__ unsigned mapa_sh(unsigned addr, unsigned rank) {
    unsigned r;
    asm("mapa.shared::cluster.u32 %0, %1, %2;" : "=r"(r) : "r"(addr), "r"(rank));
    return r;
}
__device__ __forceinline__ void st_cluster_v2(unsigned addr, float x, float y) {
    asm volatile("st.shared::cluster.v2.f32 [%0], {%1, %2};"
                 :: "r"(addr), "f"(x), "f"(y) : "memory");
}
__device__ __forceinline__ void cluster_arrive() {
    asm volatile("barrier.cluster.arrive.aligned;" ::: "memory");
}
__device__ __forceinline__ void cluster_wait() {
    asm volatile("barrier.cluster.wait.aligned;" ::: "memory");
}
__device__ __forceinline__ void cluster_sync_full() {
    cluster_arrive(); cluster_wait();
}
__device__ __forceinline__ unsigned ctarank() {
    unsigned r;
    asm("mov.u32 %0, %%cluster_ctarank;" : "=r"(r));
    return r;
}
__device__ __forceinline__ float sigmoid_f(float x) {
    return __fdividef(1.f, 1.f + __expf(-x));
}
__device__ __forceinline__ float tanh_f(float x) {
    return 1.f - __fdividef(2.f, __expf(2.f * x) + 1.f);
}
__device__ __forceinline__ void cp_async16(unsigned sdst, const void* gsrc) {
    asm volatile("cp.async.cg.shared.global [%0], [%1], 16;"
                 :: "r"(sdst), "l"(gsrc) : "memory");
}
#define CP_COMMIT()  asm volatile("cp.async.commit_group;" ::: "memory")
#define CP_WAIT(n)   asm volatile("cp.async.wait_group %0;" :: "n"(n) : "memory")
#define SWZ(o) ((o) ^ (((o) >> 3) & 0x70))

// ---------------- warp-level bf16 MMA helpers ----------------------------------
__device__ __forceinline__ void ldsm_x4(unsigned* r, unsigned addr) {
    asm volatile("ldmatrix.sync.aligned.m8n8.x4.shared.b16 {%0,%1,%2,%3}, [%4];"
                 : "=r"(r[0]), "=r"(r[1]), "=r"(r[2]), "=r"(r[3]) : "r"(addr));
}
__device__ __forceinline__ void ldsm_x2(unsigned* r, unsigned addr) {
    asm volatile("ldmatrix.sync.aligned.m8n8.x2.shared.b16 {%0,%1}, [%2];"
                 : "=r"(r[0]), "=r"(r[1]) : "r"(addr));
}
__device__ __forceinline__ void mma_bf16(float* c, const unsigned* a, const unsigned* b) {
    asm volatile("mma.sync.aligned.m16n8k16.row.col.f32.bf16.bf16.f32 "
                 "{%0,%1,%2,%3}, {%4,%5,%6,%7}, {%8,%9}, {%0,%1,%2,%3};"
                 : "+f"(c[0]), "+f"(c[1]), "+f"(c[2]), "+f"(c[3])
                 : "r"(a[0]), "r"(a[1]), "r"(a[2]), "r"(a[3]),
                   "r"(b[0]), "r"(b[1]));
}

// ---------------- split-bf16 conversion: src[rows,512] -> dst[rows, hi|lo] ----
__global__ __launch_bounds__(256) void convert_split(
    const float* __restrict__ src, __nv_bfloat16* __restrict__ dst, int nelem)
{
    const int idx = (blockIdx.x * 256 + threadIdx.x) * 4;
    if (idx >= nelem) return;
    const int row = idx >> 9, col = idx & 511;
    const float4 v = *(const float4*)(src + idx);
    __nv_bfloat16 h0 = __float2bfloat16(v.x), h1 = __float2bfloat16(v.y);
    __nv_bfloat16 h2 = __float2bfloat16(v.z), h3 = __float2bfloat16(v.w);
    __nv_bfloat16 l0 = __float2bfloat16(v.x - __bfloat162float(h0));
    __nv_bfloat16 l1 = __float2bfloat16(v.y - __bfloat162float(h1));
    __nv_bfloat16 l2 = __float2bfloat16(v.z - __bfloat162float(h2));
    __nv_bfloat16 l3 = __float2bfloat16(v.w - __bfloat162float(h3));
    __nv_bfloat162* dh = (__nv_bfloat162*)(dst + (size_t)row * 1024 + col);
    __nv_bfloat162* dl = (__nv_bfloat162*)(dst + (size_t)row * 1024 + 512 + col);
    dh[0] = __nv_bfloat162(h0, h1); dh[1] = __nv_bfloat162(h2, h3);
    dl[0] = __nv_bfloat162(l0, l1); dl[1] = __nv_bfloat162(l2, l3);
}

// ---------------- HMMA GEMM: xi = A @ W^T + b ----------------------------------
// CTA 128m x 128n, 8 warps (2m x 4n), warp tile 64x32, mma.m16n8k16 bf16.
// K_eff = 1536 (hi*hi + lo*hi + hi*lo), chunks of 64 in SW128 smem, cp.async
// double-buffered. fwd+rev fused over blockIdx.
#define GT_SMEM (2 * 32768 + 1024)
__global__ __launch_bounds__(256) void gemm_mma(
    const float* __restrict__ bf_, const float* __restrict__ br_)
{
    extern __shared__ char dsm[];
    __shared__ float sbias[128];
    const unsigned sbase = (smem_u32(dsm) + 1023u) & ~1023u;

    const int tid = threadIdx.x;
    const int wid = tid >> 5, lane = tid & 31;
    const int wm = wid >> 2, wn = wid & 3;     // 2 x 4 warp grid
    const int g = lane >> 2, tig = lane & 3;

    const int bx = blockIdx.x;
    const int m_tile = bx / 12;
    const int sub = bx - m_tile * 12;
    const int dir = sub >= 6;
    const int n0 = (dir ? sub - 6 : sub) * 128;
    const int m0 = m_tile * 128;
    float* C = dir ? g_xi_r : g_xi_f;
    const __nv_bfloat16* w2 = g_w2 + (size_t)dir * G3 * 1024;
    const float* bias = dir ? br_ : bf_;

    if (tid < 128) sbias[tid] = bias[n0 + tid];

    // ldmatrix address precompute
    // A: row = wm*64 + mt*16 + (lane&15); col8 = (lane>>4)*8
    const int arow = wm * 64 + (lane & 15);
    const unsigned axm = (unsigned)(arow & 7) * 16u;          // swizzle xor mask
    const unsigned acol8 = (unsigned)(lane >> 4) * 16u;       // bytes
    // B: row = wn*32 + nt*8 + (lane&7); col8 = ((lane>>3)&1)*8 (lanes 0-15 used)
    const int brow = wn * 32 + (lane & 7);
    const unsigned bxm = (unsigned)(lane & 7) * 16u;
    const unsigned bcol8 = (unsigned)((lane >> 3) & 1) * 16u;

    float acc[4][4][4];
#pragma unroll
    for (int mt = 0; mt < 4; mt++)
#pragma unroll
        for (int nt = 0; nt < 4; nt++)
#pragma unroll
            for (int q = 0; q < 4; q++) acc[mt][nt][q] = 0.f;

    // loader: tid<128 -> A row tid; tid>=128 -> B row tid-128 (one 128B row)
    const int lrow = tid & 127;
    const int isb = tid >> 7;
    auto load_chunk = [&](int c, int buf) {
        int acol, bcol;
        if (c < 8)       { acol = c * 64;              bcol = c * 64; }
        else if (c < 16) { acol = 512 + (c - 8) * 64;  bcol = (c - 8) * 64; }
        else             { acol = (c - 16) * 64;       bcol = 512 + (c - 16) * 64; }
        const __nv_bfloat16* src = isb
            ? (w2 + (size_t)(n0 + lrow) * 1024 + bcol)
            : (g_a2 + (size_t)(m0 + lrow) * 1024 + acol);
        const unsigned dbuf = sbase + (unsigned)buf * 32768u + (unsigned)isb * 16384u;
        const unsigned rowo = (unsigned)lrow * 128u;
#pragma unroll
        for (int q = 0; q < 8; q++)
            cp_async16(dbuf + SWZ(rowo + q * 16u), src + q * 8);
        CP_COMMIT();
    };

    load_chunk(0, 0);

    for (int c = 0; c < 24; c++) {
        const int buf = c & 1;
        if (c < 23) { load_chunk(c + 1, (c + 1) & 1); CP_WAIT(1); }
        else        { CP_WAIT(0); }
        __syncthreads();

        const unsigned abuf = sbase + (unsigned)buf * 32768u;
        const unsigned bbuf = abuf + 16384u;
#pragma unroll
        for (int ks = 0; ks < 4; ks++) {
            const unsigned akc = (unsigned)(ks * 32) + acol8;
            const unsigned bkc = (unsigned)(ks * 32) + bcol8;
            unsigned af[4][4];
#pragma unroll
            for (int mt = 0; mt < 4; mt++)
                ldsm_x4(af[mt], abuf + (unsigned)(arow + mt * 16) * 128u + (akc ^ axm));
            unsigned bfr[4][2];
#pragma unroll
            for (int nt = 0; nt < 4; nt++)
                ldsm_x2(bfr[nt], bbuf + (unsigned)(brow + nt * 8) * 128u + (bkc ^ bxm));
#pragma unroll
            for (int mt = 0; mt < 4; mt++)
#pragma unroll
                for (int nt = 0; nt < 4; nt++)
                    mma_bf16(acc[mt][nt], af[mt], bfr[nt]);
        }
        __syncthreads();
    }

    // epilogue: bias + store (each thread: rows g,g+8 of each mt; cols 2tig,2tig+1)
#pragma unroll
    for (int mt = 0; mt < 4; mt++) {
        const int m = m0 + wm * 64 + mt * 16 + g;
#pragma unroll
        for (int nt = 0; nt < 4; nt++) {
            const int nloc = wn * 32 + nt * 8 + 2 * tig;
            const float b0 = sbias[nloc], b1 = sbias[nloc + 1];
            float2 v0, v1;
            v0.x = acc[mt][nt][0] + b0; v0.y = acc[mt][nt][1] + b1;
            v1.x = acc[mt][nt][2] + b0; v1.y = acc[mt][nt][3] + b1;
            *(float2*)(C + (size_t)m * G3 + n0 + nloc) = v0;
            *(float2*)(C + (size_t)(m + 8) * G3 + n0 + nloc) = v1;
        }
    }
}

// ---------------- cluster-persistent GRU recurrence (unchanged) ---------------
#define HSS 16
#define WS_FLOATS  (3 * 128 * 128)
#define HSBUF_FLOATS (256 * HSS)
#define HSBUF_BYTES  (HSBUF_FLOATS * 4)
#define GRU_SMEM_BYTES ((WS_FLOATS + 2 * HSBUF_FLOATS) * 4)

__global__ void __launch_bounds__(256, 1) __cluster_dims__(4, 1, 1)
gru_cluster(const float* __restrict__ whh_f, const float* __restrict__ whh_r,
            const float* __restrict__ bhh_f, const float* __restrict__ bhh_r,
            int layer)
{
    extern __shared__ float sm[];
    float* ws = sm;
    float* hs = sm + WS_FLOATS;

    const unsigned rank = ctarank();
    const int cid = blockIdx.x >> 2;
    const int dir = cid >> 4;
    const int bg  = cid & 15;

    float* seq = layer ? g_seq1 : g_seq0;
    const float* xi  = dir ? g_xi_r : g_xi_f;
    const float* whh = dir ? whh_r : whh_f;
    const float* bhh = dir ? bhh_r : bhh_f;
    const int zoff = dir * HID;

    const int tid  = threadIdx.x;
    const int w    = tid >> 5;
    const int lane = tid & 31;
    const int hq    = w & 3;
    const int bhalf = w >> 2;
    const int hl    = lane & 15;
    const int bpair = lane >> 4;
    const int bb    = bhalf * 8 + bpair * 4;
    const int hx2   = (hq * 16 + hl) * 2;

    {
        const int h = tid >> 2;
        const int kb = (tid & 3) * 32;
        for (int g = 0; g < 3; g++) {
            const float* wrow = whh + (size_t)(g * HID + rank * 64 + h) * HID;
#pragma unroll 4
            for (int kk = kb; kk < kb + 32; kk++) {
                float2 v = *(const float2*)(wrow + 2 * kk);
                *(float2*)&ws[(g * 128 + kk) * 128 + h * 2] = v;
            }
        }
    }
    for (int i = tid; i < HSBUF_FLOATS; i += 256) hs[i] = 0.f;
    __syncthreads();
    cluster_sync_full();

    const int hglob = rank * 64 + hq * 16 + hl;
    const float br = bhh[hglob], bz = bhh[HID + hglob], bn = bhh[2 * HID + hglob];
    unsigned dst_r[4];
    {
        const unsigned base = smem_u32(hs) + (unsigned)((hglob * HSS + bb) * 4);
#pragma unroll
        for (unsigned r = 0; r < 4; r++) dst_r[r] = mapa_sh(base, r);
    }

    float xig[3][4];
#pragma unroll
    for (int j = 0; j < 4; j++) {
        const int b = bg * 16 + bb + j;
        const int t0 = dir ? (SEQL - 1) : 0;
        const float* xp = xi + ((size_t)b * SEQL + t0) * G3 + hglob;
#pragma unroll
        for (int g = 0; g < 3; g++) xig[g][j] = __ldg(xp + g * HID);
    }

    for (int s = 0; s < SEQL; s++) {
        const int t = dir ? (SEQL - 1 - s) : s;
        const int par = s & 1;
        const float* hsr = hs + par * HSBUF_FLOATS;

        unsigned long long acc[3][2];
#pragma unroll
        for (int g = 0; g < 3; g++) { acc[g][0] = 0ull; acc[g][1] = 0ull; }

#pragma unroll 4
        for (int kk = 0; kk < 128; kk++) {
            const ulonglong2 ha = *(const ulonglong2*)&hsr[(2 * kk) * HSS + bb];
            const ulonglong2 hb = *(const ulonglong2*)&hsr[(2 * kk + 1) * HSS + bb];
#pragma unroll
            for (int g = 0; g < 3; g++) {
                const float2 wv = *(const float2*)&ws[(g * 128 + kk) * 128 + hx2];
                const unsigned long long w0 = dup2(wv.x);
                const unsigned long long w1 = dup2(wv.y);
                ffma2(acc[g][0], ha.x, w0);
                ffma2(acc[g][1], ha.y, w0);
                ffma2(acc[g][0], hb.x, w1);
                ffma2(acc[g][1], hb.y, w1);
            }
        }

        const float4 hp = *(const float4*)&hsr[hglob * HSS + bb];

        float hnew[4];
        {
            const float hpj[4] = {hp.x, hp.y, hp.z, hp.w};
#pragma unroll
            for (int p = 0; p < 2; p++) {
#pragma unroll
                for (int half = 0; half < 2; half++) {
                    const int j = 2 * p + half;
                    const float gr = (half ? f2hi(acc[0][p]) : f2lo(acc[0][p])) + br;
                    const float gz = (half ? f2hi(acc[1][p]) : f2lo(acc[1][p])) + bz;
                    const float gn = (half ? f2hi(acc[2][p]) : f2lo(acc[2][p])) + bn;
                    const float rg = sigmoid_f(xig[0][j] + gr);
                    const float zg = sigmoid_f(xig[1][j] + gz);
                    const float ng = tanh_f(xig[2][j] + rg * gn);
                    hnew[j] = (1.f - zg) * ng + zg * hpj[j];
                    const int b = bg * 16 + bb + j;
                    seq[((size_t)b * SEQL + t) * 512 + zoff + hglob] = hnew[j];
                }
            }
        }

        const unsigned boff = (unsigned)((par ^ 1) * HSBUF_BYTES);
#pragma unroll
        for (unsigned r = 0; r < 4; r++) {
            st_cluster_v2(dst_r[r] + boff + 0, hnew[0], hnew[1]);
            st_cluster_v2(dst_r[r] + boff + 8, hnew[2], hnew[3]);
        }

        cluster_arrive();

        if (s + 1 < SEQL) {
            const int tn_ = dir ? (SEQL - 2 - s) : (s + 1);
#pragma unroll
            for (int j = 0; j < 4; j++) {
                const int b = bg * 16 + bb + j;
                const float* xp = xi + ((size_t)b * SEQL + tn_) * G3 + hglob;
#pragma unroll
                for (int g = 0; g < 3; g++) xig[g][j] = __ldg(xp + g * HID);
            }
        }

        cluster_wait();
    }
}

// ---------------- heads ------------------------------------------------------
__global__ __launch_bounds__(128) void fc_heads(
    const float* __restrict__ fc1w, const float* __restrict__ fc1b,
    const float* __restrict__ fc2w, const float* __restrict__ fc2b,
    float* __restrict__ y, float* __restrict__ y2)
{
    const int bt = blockIdx.x;
    __shared__ float row[512];
    const int tid = threadIdx.x;
    const float* src = g_seq1 + (size_t)bt * 512;
    for (int i = tid; i < 512; i += 128) row[i] = src[i];
    __syncthreads();
    const int warp = tid >> 5, lane = tid & 31;
    for (int j = warp; j < 11; j += 4) {
        const float* w = (j == 10) ? fc1w : fc2w + (size_t)j * 512;
        float s = 0.f;
#pragma unroll
        for (int i = 0; i < 16; i++) s += row[lane + 32 * i] * w[lane + 32 * i];
#pragma unroll
        for (int off = 16; off; off >>= 1) s += __shfl_xor_sync(0xffffffffu, s, off);
        if (lane == 0) {
            if (j == 10) y[bt] = s + fc1b[0];
            else         y2[(size_t)bt * 10 + j] = s + fc2b[j];
        }
    }
}

__global__ __launch_bounds__(256) void softmax_y_kernel(const float* __restrict__ y) {
    const int b = blockIdx.x;
    __shared__ float sh[256];
    const int tid = threadIdx.x;
    float v = (tid < SEQL) ? y[b * SEQL + tid] : -INFINITY;
    sh[tid] = v; __syncthreads();
    for (int s = 128; s; s >>= 1) {
        if (tid < s) sh[tid] = fmaxf(sh[tid], sh[tid + s]);
        __syncthreads();
    }
    const float mx = sh[0]; __syncthreads();
    const float e = (tid < SEQL) ? __expf(v - mx) : 0.f;
    sh[tid] = e; __syncthreads();
    for (int s = 128; s; s >>= 1) {
        if (tid < s) sh[tid] += sh[tid + s];
        __syncthreads();
    }
    const float inv = 1.f / sh[0];
    if (tid < SEQL) g_p[b * SEQL + tid] = e * inv * 0.1f;
}

__global__ __launch_bounds__(256) void softmax_y2_kernel(
    const float* __restrict__ y2, float* __restrict__ y3)
{
    const int b = blockIdx.x;
    const int tid = threadIdx.x;
    __shared__ float sh[256];
    const float* src = y2 + (size_t)b * 2000;
    float mx = -INFINITY;
    for (int i = tid; i < 2000; i += 256) mx = fmaxf(mx, src[i]);
    sh[tid] = mx; __syncthreads();
    for (int s = 128; s; s >>= 1) {
        if (tid < s) sh[tid] = fmaxf(sh[tid], sh[tid + s]);
        __syncthreads();
    }
    mx = sh[0]; __syncthreads();
    float sum = 0.f;
    for (int i = tid; i < 2000; i += 256) sum += __expf(src[i] - mx);
    sh[tid] = sum; __syncthreads();
    for (int s = 128; s; s >>= 1) {
        if (tid < s) sh[tid] += sh[tid + s];
        __syncthreads();
    }
    const float inv = 1.f / sh[0];
    for (int i = tid; i < 2000; i += 256)
        y3[(size_t)b * 2000 + i] = __expf(src[i] - mx) * inv + g_p[b * SEQL + i / 10];
}

// ---------------- driver ------------------------------------------------------
extern "C" void kernel_launch(void* const* d_in, const int* in_sizes, int n_in,
                              void* d_out, int out_size) {
    (void)in_sizes; (void)n_in; (void)out_size;
    const float* x        = (const float*)d_in[0];
    const float* w_ih_l0  = (const float*)d_in[1];
    const float* w_hh_l0  = (const float*)d_in[2];
    const float* b_ih_l0  = (const float*)d_in[3];
    const float* b_hh_l0  = (const float*)d_in[4];
    const float* w_ih_l0r = (const float*)d_in[5];
    const float* w_hh_l0r = (const float*)d_in[6];
    const float* b_ih_l0r = (const float*)d_in[7];
    const float* b_hh_l0r = (const float*)d_in[8];
    const float* w_ih_l1  = (const float*)d_in[9];
    const float* w_hh_l1  = (const float*)d_in[10];
    const float* b_ih_l1  = (const float*)d_in[11];
    const float* b_hh_l1  = (const float*)d_in[12];
    const float* w_ih_l1r = (const float*)d_in[13];
    const float* w_hh_l1r = (const float*)d_in[14];
    const float* b_ih_l1r = (const float*)d_in[15];
    const float* b_hh_l1r = (const float*)d_in[16];
    const float* fc1_w    = (const float*)d_in[17];
    const float* fc1_b    = (const float*)d_in[18];
    const float* fc2_w    = (const float*)d_in[19];
    const float* fc2_b    = (const float*)d_in[20];

    float* y  = (float*)d_out;
    float* y2 = y + BL;
    float* y3 = y2 + BL * 10;

    static int configured = 0;
    if (!configured) {
        cudaFuncSetAttribute(gru_cluster, cudaFuncAttributeMaxDynamicSharedMemorySize,
                             GRU_SMEM_BYTES);
        cudaFuncSetAttribute(gemm_mma, cudaFuncAttributeMaxDynamicSharedMemorySize,
                             GT_SMEM);
        configured = 1;
    }

    __nv_bfloat16* a2p = nullptr;
    __nv_bfloat16* w2p = nullptr;
    cudaGetSymbolAddress((void**)&a2p, g_a2);
    cudaGetSymbolAddress((void**)&w2p, g_w2);
    float* seq0p = nullptr;
    cudaGetSymbolAddress((void**)&seq0p, g_seq0);

    const int A_ELEM = BL * 512;
    const int W_ELEM = G3 * 512;

    // ---- layer 0 ----
    convert_split<<<A_ELEM / 1024, 256>>>(x, a2p, A_ELEM);
    convert_split<<<W_ELEM / 1024, 256>>>(w_ih_l0,  w2p,                     W_ELEM);
    convert_split<<<W_ELEM / 1024, 256>>>(w_ih_l0r, w2p + (size_t)G3 * 1024, W_ELEM);
    gemm_mma<<<(BL / 128) * 12, 256, GT_SMEM>>>(b_ih_l0, b_ih_l0r);
    gru_cluster<<<128, 256, GRU_SMEM_BYTES>>>(w_hh_l0, w_hh_l0r, b_hh_l0, b_hh_l0r, 0);

    // ---- layer 1 ----
    convert_split<<<A_ELEM / 1024, 256>>>(seq0p, a2p, A_ELEM);
    convert_split<<<W_ELEM / 1024, 256>>>(w_ih_l1,  w2p,                     W_ELEM);
    convert_split<<<W_ELEM / 1024, 256>>>(w_ih_l1r, w2p + (size_t)G3 * 1024, W_ELEM);
    gemm_mma<<<(BL / 128) * 12, 256, GT_SMEM>>>(b_ih_l1, b_ih_l1r);
    gru_cluster<<<128, 256, GRU_SMEM_BYTES>>>(w_hh_l1, w_hh_l1r, b_hh_l1, b_hh_l1r, 1);

    // ---- heads ----
    fc_heads<<<BL, 128>>>(fc1_w, fc1_b, fc2_w, fc2_b, y, y2);
    softmax_y_kernel<<<BATCH, 256>>>(y);
    softmax_y2_kernel<<<BATCH, 256>>>(y2, y3);
}